// round 1
// baseline (speedup 1.0000x reference)
#include <cuda_runtime.h>
#include <math.h>

#define CIN    256
#define BATCH  4
#define HOUT   40
#define WOUT   40
#define HWOUT  1600
#define NTOT   (BATCH*HWOUT)   // 6400

#define BM 128
#define BN 64
#define KC 16
#define NTHREADS 256
#define AS_STRIDE (BM+4)       // 132 floats, 528B rows (16B aligned)

// scratch (no cudaMalloc allowed)
__device__ float g_f[BATCH*CIN*HWOUT];   // running feature f  [4,256,40,40]
__device__ float g_om[BATCH*48*HWOUT];   // offset/mask conv out [4,48,40,40]

// MODE: 0 = implicit-GEMM 3x3 conv (stride1 pad1), 1 = modulated deformable conv (k=4,K=16)
// EPI : 0 = +bias ; 1 = relu(v+bias)+epi_src (in-place f update) ; 2 = v+bias+epi_src (final fh add)
template<int MODE, int EPI>
__global__ __launch_bounds__(NTHREADS)
void gemm_fused(const float* __restrict__ x, int Hin, int Win,
                const float* __restrict__ wgt, const float* __restrict__ bias,
                const float* __restrict__ om,
                const float* __restrict__ epi_src,
                float* __restrict__ out,
                int Cout, int Ktot,
                int stride, int pad, int dil)
{
    __shared__ __align__(16) float As[2][KC*AS_STRIDE];
    __shared__ __align__(16) float Bs[2][KC*BN];
    __shared__ int   mYX[KC*BN];
    __shared__ float mLY[KC*BN];
    __shared__ float mLX[KC*BN];
    __shared__ float mMK[KC*BN];

    const int tid = threadIdx.x;
    const int n0  = blockIdx.x * BN;
    const int m0  = blockIdx.y * BM;
    const int b   = n0 / HWOUT;
    const int hw0 = n0 - b * HWOUT;
    const int HWin = Hin * Win;
    const float* xb = x + (size_t)b * CIN * HWin;

    // ---- deformable sampling metadata (per block, once): 16 taps x 64 positions ----
    if (MODE == 1) {
        const float* omb = om + (size_t)b * 48 * HWOUT;
        for (int i = tid; i < KC*BN; i += NTHREADS) {
            int k  = i >> 6;          // tap 0..15 (r0 multiple of 16 -> k == kk)
            int nn = i & 63;
            int hw = hw0 + nn;
            int h = hw / WOUT, w = hw - (hw / WOUT) * WOUT;
            float dy = omb[(size_t)(2*k  )*HWOUT + hw];
            float dx = omb[(size_t)(2*k+1)*HWOUT + hw];
            float mm = omb[(size_t)(32+k )*HWOUT + hw];
            mm = 1.0f / (1.0f + expf(-mm));
            float py = (float)((k >> 2) * dil + h * stride - pad) + dy;
            float px = (float)((k &  3) * dil + w * stride - pad) + dx;
            float fy = floorf(py), fx = floorf(px);
            int y0 = (int)fy, x0 = (int)fx;
            mLY[i] = py - fy;
            mLX[i] = px - fx;
            mMK[i] = mm;
            mYX[i] = (y0 << 16) | (x0 & 0xffff);
        }
    }
    __syncthreads();

    float acc[8][4];
#pragma unroll
    for (int i = 0; i < 8; i++)
#pragma unroll
        for (int j = 0; j < 4; j++) acc[i][j] = 0.f;

    const int tmi = tid >> 4;   // 0..15 -> m micro-row (8 outputs)
    const int tni = tid & 15;   // 0..15 -> n micro-col (4 outputs)
    const int NC  = Ktot / KC;

    float aR[8], bR[4], rv[16];

    // ---- stage loaders ----
    auto loadA = [&](int c, float* a) {
        int r0 = c * KC;
#pragma unroll
        for (int i = 0; i < 8; i++) {
            int e = tid + i * NTHREADS;
            int kk = e & 15, m = e >> 4;
            a[i] = (m0 + m < Cout) ? wgt[(size_t)(m0 + m) * Ktot + r0 + kk] : 0.f;
        }
    };
    auto loadB_conv = [&](int c, float* bv) {
        int r0 = c * KC;
#pragma unroll
        for (int i = 0; i < 4; i++) {
            int e  = tid * 4 + i;
            int kk = e >> 6, nn = e & 63;
            int r  = r0 + kk;
            int ci = r / 9, j = r - ci * 9;
            int hw = hw0 + nn;
            int h = hw / WOUT, w = hw - (hw / WOUT) * WOUT;
            int y = h + j / 3 - 1;
            int xx = w + (j % 3) - 1;
            bv[i] = (y >= 0 && y < Hin && xx >= 0 && xx < Win)
                    ? xb[(size_t)ci * HWin + y * Win + xx] : 0.f;
        }
    };
    auto loadB_def_raw = [&](int c, float* r4) {
        int ci = (c * KC) >> 4;
        const float* plane = xb + (size_t)ci * HWin;
#pragma unroll
        for (int i = 0; i < 4; i++) {
            int e = tid * 4 + i;             // == kk*64+nn flat index into meta
            int yx = mYX[e];
            int y0 = yx >> 16;
            int x0 = (int)(short)(yx & 0xffff);
            int y1 = y0 + 1, x1 = x0 + 1;
            bool yv0 = (y0 >= 0) & (y0 < Hin);
            bool yv1 = (y1 >= 0) & (y1 < Hin);
            bool xv0 = (x0 >= 0) & (x0 < Win);
            bool xv1 = (x1 >= 0) & (x1 < Win);
            r4[i*4+0] = (yv0 & xv0) ? plane[y0 * Win + x0] : 0.f;
            r4[i*4+1] = (yv0 & xv1) ? plane[y0 * Win + x1] : 0.f;
            r4[i*4+2] = (yv1 & xv0) ? plane[y1 * Win + x0] : 0.f;
            r4[i*4+3] = (yv1 & xv1) ? plane[y1 * Win + x1] : 0.f;
        }
    };
    auto combine_def = [&](const float* r4, float* bv) {
#pragma unroll
        for (int i = 0; i < 4; i++) {
            int e = tid * 4 + i;
            float ly = mLY[e], lx = mLX[e], mm = mMK[e];
            float top = (1.f - lx) * r4[i*4+0] + lx * r4[i*4+1];
            float bot = (1.f - lx) * r4[i*4+2] + lx * r4[i*4+3];
            bv[i] = ((1.f - ly) * top + ly * bot) * mm;
        }
    };
    auto storeChunk = [&](int buf, const float* a, const float* bv) {
#pragma unroll
        for (int i = 0; i < 8; i++) {
            int e = tid + i * NTHREADS;
            int kk = e & 15, m = e >> 4;
            As[buf][kk * AS_STRIDE + m] = a[i];
        }
        *(float4*)&Bs[buf][tid * 4] = make_float4(bv[0], bv[1], bv[2], bv[3]);
    };

    // ---- prologue ----
    loadA(0, aR);
    if (MODE == 0) loadB_conv(0, bR);
    else { loadB_def_raw(0, rv); combine_def(rv, bR); }
    storeChunk(0, aR, bR);
    __syncthreads();

    // ---- mainloop (double buffered) ----
    for (int c = 0; c < NC; c++) {
        int cur = c & 1;
        bool nxt = (c + 1 < NC);
        if (nxt) {
            loadA(c + 1, aR);
            if (MODE == 0) loadB_conv(c + 1, bR);
            else           loadB_def_raw(c + 1, rv);
        }
#pragma unroll
        for (int kk = 0; kk < KC; kk++) {
            float4 a0 = *(const float4*)&As[cur][kk * AS_STRIDE + tmi * 8];
            float4 a1 = *(const float4*)&As[cur][kk * AS_STRIDE + tmi * 8 + 4];
            float4 b4 = *(const float4*)&Bs[cur][kk * BN + tni * 4];
            float am[8] = {a0.x,a0.y,a0.z,a0.w,a1.x,a1.y,a1.z,a1.w};
            float bn[4] = {b4.x,b4.y,b4.z,b4.w};
#pragma unroll
            for (int i = 0; i < 8; i++)
#pragma unroll
                for (int j = 0; j < 4; j++)
                    acc[i][j] += am[i] * bn[j];
        }
        if (nxt) {
            if (MODE == 1) combine_def(rv, bR);
            storeChunk(cur ^ 1, aR, bR);
        }
        __syncthreads();
    }

    // ---- epilogue ----
#pragma unroll
    for (int i = 0; i < 8; i++) {
        int co = m0 + tmi * 8 + i;
        if (co < Cout) {
            float bv = bias[co];
            size_t base = ((size_t)b * Cout + co) * HWOUT + hw0 + tni * 4;
#pragma unroll
            for (int j = 0; j < 4; j++) {
                float v = acc[i][j] + bv;
                if (EPI == 1)      v = fmaxf(v, 0.f) + epi_src[base + j];
                else if (EPI == 2) v = v + epi_src[base + j];
                out[base + j] = v;
            }
        }
    }
}

extern "C" void kernel_launch(void* const* d_in, const int* in_sizes, int n_in,
                              void* d_out, int out_size)
{
    const float* f0 = (const float*)d_in[0];   // [4,256,160,160]
    const float* f1 = (const float*)d_in[1];   // [4,256,80,80]
    const float* f2 = (const float*)d_in[2];   // [4,256,40,40]
    const float* com_w[2] = {(const float*)d_in[3], (const float*)d_in[5]};
    const float* com_b[2] = {(const float*)d_in[4], (const float*)d_in[6]};
    const float* dcn_w[2] = {(const float*)d_in[7], (const float*)d_in[9]};
    const float* dcn_b[2] = {(const float*)d_in[8], (const float*)d_in[10]};
    const float* res_w = (const float*)d_in[11];
    const float* res_b = (const float*)d_in[12];
    float* out = (float*)d_out;

    float *gf, *gom;
    cudaGetSymbolAddress((void**)&gf,  g_f);
    cudaGetSymbolAddress((void**)&gom, g_om);

    // f = fh = f2
    cudaMemcpyAsync(gf, f2, sizeof(float) * BATCH * CIN * HWOUT,
                    cudaMemcpyDeviceToDevice);

    const int gridN = NTOT / BN;   // 100
    dim3 blk(NTHREADS);

    const float* feats[2] = {f1, f0};
    const int Hins[2]    = {80, 160};
    const int strides[2] = {2, 4};
    const int pads[2]    = {1, 3};
    const int dils[2]    = {3, 3};   // placeholder, set below
    (void)dils;
    const int dil_[2] = {1, 3};

    for (int rep = 0; rep < 2; rep++) {
        for (int l = 0; l < 2; l++) {
            // om = conv3x3(f, com_w[l]) + com_b[l]   (Cout=48, Ktot=2304)
            gemm_fused<0,0><<<dim3(gridN, 1), blk>>>(
                gf, HOUT, WOUT, com_w[l], com_b[l], nullptr, nullptr,
                gom, 48, CIN * 9, 1, 1, 1);
            // f = relu(deform(features, om, dcn_w[l]) + b) + f   (in place)
            gemm_fused<1,1><<<dim3(gridN, 2), blk>>>(
                feats[l], Hins[l], Hins[l], dcn_w[l], dcn_b[l], gom,
                gf, gf, CIN, CIN * 16, strides[l], pads[l], dil_[l]);
        }
    }
    // out = fh + conv3x3(f, res_w) + res_b
    gemm_fused<0,2><<<dim3(gridN, 2), blk>>>(
        gf, HOUT, WOUT, res_w, res_b, nullptr, f2,
        out, CIN, CIN * 9, 1, 1, 1);
}

// round 3
// speedup vs baseline: 1.2709x; 1.2709x over previous
#include <cuda_runtime.h>
#include <cuda_bf16.h>
#include <math.h>
#include <stdint.h>

#define WOUT 40
#define HWOUT 1600
#define CIN 256
#define BATCH 4

#define BM 128
#define BN 64
#define KC 64                 // bf16 k per chunk (128B rows)
#define NTHREADS 256
#define KDEF (CIN*16)         // 4096
#define KCONV (CIN*9)         // 2304

// dynamic smem layout (bytes)
#define OFF_META 0                       // 16KB: mYX/mLY/mLX/mMK (4KB each)
#define OFF_A    16384                   // 2buf x 2fmt x 16KB
#define OFF_B    (OFF_A + 4*16384)      // 2buf x 2fmt x 8KB
#define SMEM_TOTAL (OFF_B + 4*8192)     // 114688 B

// ---------------- device scratch ----------------
__device__ float g_f[BATCH*CIN*HWOUT];
__device__ float g_om[BATCH*48*HWOUT];
__device__ __align__(16) __nv_bfloat16 g_wdef[2*2*256*KDEF];
__device__ __align__(16) __nv_bfloat16 g_wcom[2*2*128*KCONV];
__device__ __align__(16) __nv_bfloat16 g_wres[2*256*KCONV];

__device__ __forceinline__ uint32_t smem_u32(const void* p) {
    uint32_t a;
    asm("{ .reg .u64 t; cvta.to.shared.u64 t, %1; cvt.u32.u64 %0, t; }" : "=r"(a) : "l"(p));
    return a;
}
__device__ __forceinline__ uint32_t sw128(uint32_t o) { return o ^ ((o >> 3) & 0x70); }

__device__ __forceinline__ void ldsm4(uint32_t* r, uint32_t addr) {
    asm volatile("ldmatrix.sync.aligned.m8n8.x4.shared.b16 {%0,%1,%2,%3}, [%4];"
        : "=r"(r[0]), "=r"(r[1]), "=r"(r[2]), "=r"(r[3]) : "r"(addr));
}
__device__ __forceinline__ void mma16816(float* c, const uint32_t* a, uint32_t b0, uint32_t b1) {
    asm volatile("mma.sync.aligned.m16n8k16.row.col.f32.bf16.bf16.f32 "
        "{%0,%1,%2,%3},{%4,%5,%6,%7},{%8,%9},{%0,%1,%2,%3};"
        : "+f"(c[0]), "+f"(c[1]), "+f"(c[2]), "+f"(c[3])
        : "r"(a[0]), "r"(a[1]), "r"(a[2]), "r"(a[3]), "r"(b0), "r"(b1));
}

// ---------------- weight prep: fp32 -> bf16 hi/lo, pad rows ----------------
__global__ void prep_w(const float* __restrict__ w, __nv_bfloat16* __restrict__ hi,
                       __nv_bfloat16* __restrict__ lo, int Cout, int Mpad, int Ktot)
{
    int i = blockIdx.x * blockDim.x + threadIdx.x;
    if (i >= Mpad * Ktot) return;
    int row = i / Ktot;
    float v = (row < Cout) ? w[i] : 0.f;
    __nv_bfloat16 h = __float2bfloat16(v);
    hi[i] = h;
    lo[i] = __float2bfloat16(v - __bfloat162float(h));
}

// MODE 0: implicit-GEMM 3x3 conv (s1 p1).  MODE 1: modulated deformable conv (k=4, K=16).
// EPI 0: +bias ; 1: relu(v+bias)+epi_src ; 2: v+bias+epi_src
template<int MODE, int EPI>
__global__ void __launch_bounds__(NTHREADS, 1)
tc_gemm(const float* __restrict__ x, int Hin, int Win,
        const __nv_bfloat16* __restrict__ whi, const __nv_bfloat16* __restrict__ wlo,
        const float* __restrict__ bias, const float* __restrict__ om,
        const float* __restrict__ epi_src, float* __restrict__ out,
        int Cout, int Ktot, int stride, int pad, int dil)
{
    extern __shared__ __align__(1024) char smem[];
    const uint32_t sb = smem_u32(smem);
    const int tid = threadIdx.x;
    const int wid = tid >> 5, lid = tid & 31;
    const int n0 = blockIdx.x * BN;
    const int m0 = blockIdx.y * BM;
    const int b  = n0 / HWOUT;
    const int hw0 = n0 - b * HWOUT;
    const int HWin = Hin * Win;
    const float* xb = x + (size_t)b * CIN * HWin;

    int*   mYX = (int*)  (smem + OFF_META);
    float* mLY = (float*)(smem + OFF_META + 4096);
    float* mLX = (float*)(smem + OFF_META + 8192);
    float* mMK = (float*)(smem + OFF_META + 12288);

    if (MODE == 1) {
        const float* omb = om + (size_t)b * 48 * HWOUT;
        for (int i = tid; i < 1024; i += NTHREADS) {   // 16 taps x 64 pixels
            int k = i >> 6, nn = i & 63;
            int hw = hw0 + nn;
            int h = hw / WOUT, w = hw - h * WOUT;
            float dy = omb[(size_t)(2*k  )*HWOUT + hw];
            float dx = omb[(size_t)(2*k+1)*HWOUT + hw];
            float mm = omb[(size_t)(32+k )*HWOUT + hw];
            mm = 1.0f / (1.0f + expf(-mm));
            float py = (float)((k >> 2) * dil + h * stride - pad) + dy;
            float px = (float)((k &  3) * dil + w * stride - pad) + dx;
            float fy = floorf(py), fx = floorf(px);
            mLY[i] = py - fy; mLX[i] = px - fx; mMK[i] = mm;
            mYX[i] = (((int)fy) << 16) | (((int)fx) & 0xffff);
        }
        __syncthreads();
    }

    float acc[2][4][4];
#pragma unroll
    for (int i = 0; i < 2; i++)
#pragma unroll
        for (int j = 0; j < 4; j++)
#pragma unroll
            for (int q = 0; q < 4; q++) acc[i][j][q] = 0.f;

    const int NC = Ktot / KC;
    const int m0w = (wid >> 1) * 32;
    const int n0w = (wid & 1) * 32;

    // gather + convert + store one chunk into buffer `buf`
    auto gather = [&](int c, int buf) {
        // A: 2 fmt x 128 rows x 8 16B-groups
        const int k0 = c * KC;
#pragma unroll
        for (int s = 0; s < 8; s++) {
            int f = tid + s * NTHREADS;
            int fmt = f >> 10;
            int rem = f & 1023;
            int r = rem >> 3, j = rem & 7;
            const __nv_bfloat16* src = fmt ? wlo : whi;
            uint4 vv = *(const uint4*)(src + (size_t)(m0 + r) * Ktot + k0 + j * 8);
            *(uint4*)(smem + OFF_A + (buf*2 + fmt) * 16384 + sw128((uint32_t)(r*128 + j*16))) = vv;
        }
        // B: 64 px x 8 groups of 8 k
#pragma unroll
        for (int i2 = 0; i2 < 2; i2++) {
            int G = tid + i2 * NTHREADS;
            int p = G >> 3, j = G & 7;
            float v[8];
            if (MODE == 1) {
                int ci = c * 4 + (j >> 1);
                const float* plane = xb + (size_t)ci * HWin;
                int tb = (j & 1) * 8;
#pragma unroll
                for (int t = 0; t < 8; t++) {
                    int mi = (tb + t) * 64 + p;
                    int yx = mYX[mi];
                    int y0 = yx >> 16;
                    int x0 = (int)(short)(yx & 0xffff);
                    float ly = mLY[mi], lx = mLX[mi], mk = mMK[mi];
                    int y1 = y0 + 1, x1 = x0 + 1;
                    bool yv0 = (y0 >= 0) & (y0 < Hin), yv1 = (y1 >= 0) & (y1 < Hin);
                    bool xv0 = (x0 >= 0) & (x0 < Win), xv1 = (x1 >= 0) & (x1 < Win);
                    float s00 = (yv0 & xv0) ? plane[y0 * Win + x0] : 0.f;
                    float s01 = (yv0 & xv1) ? plane[y0 * Win + x1] : 0.f;
                    float s10 = (yv1 & xv0) ? plane[y1 * Win + x0] : 0.f;
                    float s11 = (yv1 & xv1) ? plane[y1 * Win + x1] : 0.f;
                    float top = (1.f - lx) * s00 + lx * s01;
                    float bot = (1.f - lx) * s10 + lx * s11;
                    v[t] = ((1.f - ly) * top + ly * bot) * mk;
                }
            } else {
                int hw = hw0 + p;
                int h = hw / WOUT, w = hw - h * WOUT;
#pragma unroll
                for (int t = 0; t < 8; t++) {
                    int k = c * KC + j * 8 + t;
                    int ci = k / 9, jj = k - ci * 9;
                    int y  = h + jj / 3 - 1;
                    int xx = w + (jj - (jj / 3) * 3) - 1;
                    v[t] = (y >= 0 && y < Hin && xx >= 0 && xx < Win)
                         ? xb[(size_t)ci * HWin + y * Win + xx] : 0.f;
                }
            }
            uint32_t hi4[4], lo4[4];
#pragma unroll
            for (int q = 0; q < 4; q++) {
                __nv_bfloat162 hh = __floats2bfloat162_rn(v[2*q], v[2*q+1]);
                float l0 = v[2*q]   - __bfloat162float(hh.x);
                float l1 = v[2*q+1] - __bfloat162float(hh.y);
                __nv_bfloat162 ll = __floats2bfloat162_rn(l0, l1);
                hi4[q] = *(uint32_t*)&hh;
                lo4[q] = *(uint32_t*)&ll;
            }
            uint32_t so = sw128((uint32_t)(p * 128 + j * 16));
            *(uint4*)(smem + OFF_B + (buf*2 + 0) * 8192 + so) = make_uint4(hi4[0], hi4[1], hi4[2], hi4[3]);
            *(uint4*)(smem + OFF_B + (buf*2 + 1) * 8192 + so) = make_uint4(lo4[0], lo4[1], lo4[2], lo4[3]);
        }
    };

    // precomputed per-lane ldmatrix offsets (within a tile)
    const uint32_t aOff = (uint32_t)((m0w + (lid & 15)) * 128 + (lid >> 4) * 16);
    const uint32_t bOff = (uint32_t)((n0w + (lid & 7) + ((lid >> 4) & 1) * 8) * 128 + ((lid >> 3) & 1) * 16);

    gather(0, 0);
    __syncthreads();

    for (int c = 0; c < NC; c++) {
        const int buf = c & 1;
        if (c + 1 < NC) gather(c + 1, buf ^ 1);

        const uint32_t sAh = sb + OFF_A + (buf*2 + 0) * 16384;
        const uint32_t sAl = sb + OFF_A + (buf*2 + 1) * 16384;
        const uint32_t sBh = sb + OFF_B + (buf*2 + 0) * 8192;
        const uint32_t sBl = sb + OFF_B + (buf*2 + 1) * 8192;

#pragma unroll
        for (int ks = 0; ks < 4; ks++) {
            uint32_t ah[2][4], al[2][4], bh[2][4], bl[2][4];
#pragma unroll
            for (int i = 0; i < 2; i++) {
                ldsm4(ah[i], sAh + sw128(aOff + (uint32_t)(i * 2048 + ks * 32)));
                ldsm4(al[i], sAl + sw128(aOff + (uint32_t)(i * 2048 + ks * 32)));
            }
#pragma unroll
            for (int j = 0; j < 2; j++) {
                ldsm4(bh[j], sBh + sw128(bOff + (uint32_t)(j * 2048 + ks * 32)));
                ldsm4(bl[j], sBl + sw128(bOff + (uint32_t)(j * 2048 + ks * 32)));
            }
#pragma unroll
            for (int i = 0; i < 2; i++)
#pragma unroll
                for (int jn = 0; jn < 4; jn++) {
                    int jp = jn >> 1, sel = (jn & 1) * 2;
                    mma16816(acc[i][jn], ah[i], bh[jp][sel], bh[jp][sel + 1]);
                    mma16816(acc[i][jn], ah[i], bl[jp][sel], bl[jp][sel + 1]);
                    mma16816(acc[i][jn], al[i], bh[jp][sel], bh[jp][sel + 1]);
                }
        }
        __syncthreads();
    }

    // ---- epilogue: fragments -> gmem ----
#pragma unroll
    for (int i = 0; i < 2; i++) {
        int row0 = m0 + m0w + i * 16 + (lid >> 2);
#pragma unroll
        for (int half = 0; half < 2; half++) {
            int co = row0 + half * 8;
            if (co >= Cout) continue;
            float bv = bias[co];
            size_t rbase = ((size_t)b * Cout + co) * HWOUT + hw0 + n0w + (lid & 3) * 2;
#pragma unroll
            for (int jn = 0; jn < 4; jn++) {
                float v0 = acc[i][jn][half * 2 + 0] + bv;
                float v1 = acc[i][jn][half * 2 + 1] + bv;
                size_t o = rbase + jn * 8;
                if (EPI == 1) {
                    float2 s = *(const float2*)(epi_src + o);
                    v0 = fmaxf(v0, 0.f) + s.x; v1 = fmaxf(v1, 0.f) + s.y;
                } else if (EPI == 2) {
                    float2 s = *(const float2*)(epi_src + o);
                    v0 += s.x; v1 += s.y;
                }
                *(float2*)(out + o) = make_float2(v0, v1);
            }
        }
    }
}

extern "C" void kernel_launch(void* const* d_in, const int* in_sizes, int n_in,
                              void* d_out, int out_size)
{
    const float* f0 = (const float*)d_in[0];
    const float* f1 = (const float*)d_in[1];
    const float* f2 = (const float*)d_in[2];
    const float* com_w[2] = {(const float*)d_in[3], (const float*)d_in[5]};
    const float* com_b[2] = {(const float*)d_in[4], (const float*)d_in[6]};
    const float* dcn_w[2] = {(const float*)d_in[7], (const float*)d_in[9]};
    const float* dcn_b[2] = {(const float*)d_in[8], (const float*)d_in[10]};
    const float* res_w = (const float*)d_in[11];
    const float* res_b = (const float*)d_in[12];
    float* out = (float*)d_out;

    float *gf, *gom;
    __nv_bfloat16 *wdef, *wcom, *wres;
    cudaGetSymbolAddress((void**)&gf,   g_f);
    cudaGetSymbolAddress((void**)&gom,  g_om);
    cudaGetSymbolAddress((void**)&wdef, g_wdef);
    cudaGetSymbolAddress((void**)&wcom, g_wcom);
    cudaGetSymbolAddress((void**)&wres, g_wres);

    cudaFuncSetAttribute(tc_gemm<0,0>, cudaFuncAttributeMaxDynamicSharedMemorySize, SMEM_TOTAL);
    cudaFuncSetAttribute(tc_gemm<1,1>, cudaFuncAttributeMaxDynamicSharedMemorySize, SMEM_TOTAL);
    cudaFuncSetAttribute(tc_gemm<0,2>, cudaFuncAttributeMaxDynamicSharedMemorySize, SMEM_TOTAL);

    cudaMemcpyAsync(gf, f2, sizeof(float) * BATCH * CIN * HWOUT, cudaMemcpyDeviceToDevice);

    const int nd = 256 * KDEF;
    const int nc = 128 * KCONV;
    const int nr = 256 * KCONV;
    for (int l = 0; l < 2; l++) {
        prep_w<<<(2*nd + 255) / 256, 256>>>(dcn_w[l], wdef + (size_t)l*2*nd, wdef + (size_t)l*2*nd + nd, 256, 256, KDEF);
        prep_w<<<(2*nc + 255) / 256, 256>>>(com_w[l], wcom + (size_t)l*2*nc, wcom + (size_t)l*2*nc + nc,  48, 128, KCONV);
    }
    prep_w<<<(2*nr + 255) / 256, 256>>>(res_w, wres, wres + nr, 256, 256, KCONV);

    const float* feats[2] = {f1, f0};
    const int Hins[2]    = {80, 160};
    const int strides[2] = {2, 4};
    const int pads[2]    = {1, 3};
    const int dils[2]    = {1, 3};

    for (int rep = 0; rep < 2; rep++) {
        for (int l = 0; l < 2; l++) {
            tc_gemm<0,0><<<dim3(100, 1), NTHREADS, SMEM_TOTAL>>>(
                gf, 40, 40,
                wcom + (size_t)l*2*nc, wcom + (size_t)l*2*nc + nc,
                com_b[l], nullptr, nullptr, gom, 48, KCONV, 1, 1, 1);
            tc_gemm<1,1><<<dim3(100, 2), NTHREADS, SMEM_TOTAL>>>(
                feats[l], Hins[l], Hins[l],
                wdef + (size_t)l*2*nd, wdef + (size_t)l*2*nd + nd,
                dcn_b[l], gom, gf, gf, 256, KDEF, strides[l], pads[l], dils[l]);
        }
    }
    tc_gemm<0,2><<<dim3(100, 2), NTHREADS, SMEM_TOTAL>>>(
        gf, 40, 40, wres, wres + nr, res_b, nullptr, f2, out, 256, KCONV, 1, 1, 1);
}

// round 4
// speedup vs baseline: 1.6963x; 1.3347x over previous
#include <cuda_runtime.h>
#include <cuda_bf16.h>
#include <math.h>
#include <stdint.h>

#define WOUT 40
#define HWOUT 1600
#define CIN 256
#define BATCH 4

#define BM 128
#define BN 64
#define KC 64
#define NTHREADS 256
#define KDEF (CIN*16)
#define KCONV (CIN*9)

// dynamic smem layout (bytes)
#define OFF_A    0                       // 2buf x 2fmt x 16KB = 64KB
#define OFF_B    65536                   // 2buf x 2fmt x 8KB  = 32KB
#define OFF_META 98304                   // mA 4KB, mDX 4KB, mDY 4KB, mW 16KB
#define SMEM_CONV 98304
#define SMEM_DEF  126976

// ---------------- device scratch ----------------
__device__ float g_f[BATCH*CIN*HWOUT];
__device__ float g_om[BATCH*48*HWOUT];
__device__ __align__(16) __nv_bfloat16 g_wdef[2*2*256*KDEF];
__device__ __align__(16) __nv_bfloat16 g_wcom[2*2*128*KCONV];
__device__ __align__(16) __nv_bfloat16 g_wres[2*256*KCONV];

__device__ __forceinline__ uint32_t smem_u32(const void* p) {
    uint32_t a;
    asm("{ .reg .u64 t; cvta.to.shared.u64 t, %1; cvt.u32.u64 %0, t; }" : "=r"(a) : "l"(p));
    return a;
}
__device__ __forceinline__ uint32_t sw128(uint32_t o) { return o ^ ((o >> 3) & 0x70); }

__device__ __forceinline__ void ldsm4(uint32_t* r, uint32_t addr) {
    asm volatile("ldmatrix.sync.aligned.m8n8.x4.shared.b16 {%0,%1,%2,%3}, [%4];"
        : "=r"(r[0]), "=r"(r[1]), "=r"(r[2]), "=r"(r[3]) : "r"(addr));
}
__device__ __forceinline__ void mma16816(float* c, const uint32_t* a, uint32_t b0, uint32_t b1) {
    asm volatile("mma.sync.aligned.m16n8k16.row.col.f32.bf16.bf16.f32 "
        "{%0,%1,%2,%3},{%4,%5,%6,%7},{%8,%9},{%0,%1,%2,%3};"
        : "+f"(c[0]), "+f"(c[1]), "+f"(c[2]), "+f"(c[3])
        : "r"(a[0]), "r"(a[1]), "r"(a[2]), "r"(a[3]), "r"(b0), "r"(b1));
}

__global__ void prep_w(const float* __restrict__ w, __nv_bfloat16* __restrict__ hi,
                       __nv_bfloat16* __restrict__ lo, int Cout, int Mpad, int Ktot)
{
    int i = blockIdx.x * blockDim.x + threadIdx.x;
    if (i >= Mpad * Ktot) return;
    int row = i / Ktot;
    float v = (row < Cout) ? w[i] : 0.f;
    __nv_bfloat16 h = __float2bfloat16(v);
    hi[i] = h;
    lo[i] = __float2bfloat16(v - __bfloat162float(h));
}

// MODE 0: implicit-GEMM 3x3 conv (s1 p1).  MODE 1: modulated deformable conv (k=4, K=16).
// EPI 0: +bias ; 1: relu(v+bias)+epi_src ; 2: v+bias+epi_src
template<int MODE, int EPI>
__global__ void __launch_bounds__(NTHREADS)
tc_gemm(const float* __restrict__ x, int Hin, int Win,
        const __nv_bfloat16* __restrict__ whi, const __nv_bfloat16* __restrict__ wlo,
        const float* __restrict__ bias, const float* __restrict__ om,
        const float* __restrict__ epi_src, float* __restrict__ out,
        int Cout, int Ktot, int stride, int pad, int dil)
{
    extern __shared__ __align__(1024) char smem[];
    const uint32_t sb = smem_u32(smem);
    const int tid = threadIdx.x;
    const int wid = tid >> 5, lid = tid & 31;
    const int n0 = blockIdx.x * BN;
    const int m0 = blockIdx.y * BM;
    const int b  = n0 / HWOUT;
    const int hw0 = n0 - b * HWOUT;
    const int HWin = Hin * Win;
    const float* xb = x + (size_t)b * CIN * HWin;

    int*    mA  = (int*)   (smem + OFF_META);
    int*    mDX = (int*)   (smem + OFF_META + 4096);
    int*    mDY = (int*)   (smem + OFF_META + 8192);
    float4* mW  = (float4*)(smem + OFF_META + 12288);

    // ---- per-CTA sampling metadata: clamped addrs + folded weights ----
    if (MODE == 1) {
        const float* omb = om + (size_t)b * 48 * HWOUT;
        for (int i = tid; i < 1024; i += NTHREADS) {   // 16 taps x 64 px
            int k = i >> 6, nn = i & 63;
            int hw = hw0 + nn;
            int h = hw / WOUT, w = hw - h * WOUT;
            float dy = omb[(size_t)(2*k  )*HWOUT + hw];
            float dx = omb[(size_t)(2*k+1)*HWOUT + hw];
            float mm = omb[(size_t)(32+k )*HWOUT + hw];
            mm = 1.0f / (1.0f + expf(-mm));
            float py = (float)((k >> 2) * dil + h * stride - pad) + dy;
            float px = (float)((k &  3) * dil + w * stride - pad) + dx;
            float fy = floorf(py), fx = floorf(px);
            int y0 = (int)fy, x0 = (int)fx;
            int y1 = y0 + 1, x1 = x0 + 1;
            float ly = py - fy, lx = px - fx;
            float v00 = ((y0 >= 0) & (y0 < Hin) & (x0 >= 0) & (x0 < Win)) ? 1.f : 0.f;
            float v01 = ((y0 >= 0) & (y0 < Hin) & (x1 >= 0) & (x1 < Win)) ? 1.f : 0.f;
            float v10 = ((y1 >= 0) & (y1 < Hin) & (x0 >= 0) & (x0 < Win)) ? 1.f : 0.f;
            float v11 = ((y1 >= 0) & (y1 < Hin) & (x1 >= 0) & (x1 < Win)) ? 1.f : 0.f;
            int yc0 = min(max(y0, 0), Hin-1), yc1 = min(max(y1, 0), Hin-1);
            int xc0 = min(max(x0, 0), Win-1), xc1 = min(max(x1, 0), Win-1);
            mA[i]  = yc0 * Win + xc0;
            mDX[i] = xc1 - xc0;
            mDY[i] = (yc1 - yc0) * Win;
            float4 w4;
            w4.x = (1.f-ly)*(1.f-lx)*mm*v00;
            w4.y = (1.f-ly)*lx      *mm*v01;
            w4.z = ly      *(1.f-lx)*mm*v10;
            w4.w = ly      *lx      *mm*v11;
            mW[i] = w4;
        }
        __syncthreads();
    }

    float acc[2][4][4];
#pragma unroll
    for (int i = 0; i < 2; i++)
#pragma unroll
        for (int j = 0; j < 4; j++)
#pragma unroll
            for (int q = 0; q < 4; q++) acc[i][j][q] = 0.f;

    const int NC = Ktot / KC;
    const int m0w = (wid >> 1) * 32;
    const int n0w = (wid & 1) * 32;

    auto loadA_async = [&](int c, int buf) {
        const int k0 = c * KC;
#pragma unroll
        for (int s = 0; s < 8; s++) {
            int f = tid + s * NTHREADS;
            int fmt = f >> 10;
            int rem = f & 1023;
            int r = rem >> 3, j = rem & 7;
            const __nv_bfloat16* src = fmt ? wlo : whi;
            uint32_t dst = sb + OFF_A + (uint32_t)((buf*2 + fmt) * 16384) + sw128((uint32_t)(r*128 + j*16));
            const void* gsrc = src + (size_t)(m0 + r) * Ktot + k0 + j * 8;
            asm volatile("cp.async.cg.shared.global [%0], [%1], 16;" :: "r"(dst), "l"(gsrc));
        }
        asm volatile("cp.async.commit_group;");
    };

    // deform B gather: warp = (channel ciL, pixel half), lanes = consecutive pixels
    auto gatherB_def = [&](int c, int buf) {
        const int ciL = wid & 3;
        const int px  = (wid >> 2) * 32 + lid;
        const float* plane = xb + (size_t)(c * 4 + ciL) * HWin;
        uint32_t hv[8], lv[8];
#pragma unroll
        for (int tp = 0; tp < 8; tp++) {
            float vv[2];
#pragma unroll
            for (int u = 0; u < 2; u++) {
                int i = (tp * 2 + u) * 64 + px;
                int a00 = mA[i];
                int dX = mDX[i], dY = mDY[i];
                float4 w4 = mW[i];
                float s00 = plane[a00];
                float s01 = plane[a00 + dX];
                float s10 = plane[a00 + dY];
                float s11 = plane[a00 + dY + dX];
                vv[u] = w4.x*s00 + w4.y*s01 + w4.z*s10 + w4.w*s11;
            }
            __nv_bfloat162 hh = __floats2bfloat162_rn(vv[0], vv[1]);
            float l0 = vv[0] - __bfloat162float(hh.x);
            float l1 = vv[1] - __bfloat162float(hh.y);
            __nv_bfloat162 ll = __floats2bfloat162_rn(l0, l1);
            hv[tp] = *(uint32_t*)&hh;
            lv[tp] = *(uint32_t*)&ll;
        }
        uint32_t rowbase = (uint32_t)(px * 128 + ciL * 32);
#pragma unroll
        for (int tp = 0; tp < 8; tp++) {
            uint32_t so = sw128(rowbase + tp * 4);
            *(uint32_t*)(smem + OFF_B + (buf*2 + 0) * 8192 + so) = hv[tp];
            *(uint32_t*)(smem + OFF_B + (buf*2 + 1) * 8192 + so) = lv[tp];
        }
    };

    // conv B gather: warp = 8 k-values, lanes = consecutive pixels
    auto gatherB_conv = [&](int c, int buf) {
#pragma unroll
        for (int ph = 0; ph < 2; ph++) {
            int px = ph * 32 + lid;
            int hw = hw0 + px;
            int h = hw / WOUT, w_ = hw - h * WOUT;
            uint32_t rowbase = (uint32_t)(px * 128 + wid * 16);
#pragma unroll
            for (int q = 0; q < 4; q++) {
                float v[2];
#pragma unroll
                for (int u = 0; u < 2; u++) {
                    int k = c * KC + wid * 8 + q * 2 + u;
                    int ci = k / 9, jj = k - ci * 9;
                    int y  = h + jj / 3 - 1;
                    int xx = w_ + (jj - (jj / 3) * 3) - 1;
                    v[u] = (y >= 0 && y < Hin && xx >= 0 && xx < Win)
                         ? xb[(size_t)ci * HWin + y * Win + xx] : 0.f;
                }
                __nv_bfloat162 hh = __floats2bfloat162_rn(v[0], v[1]);
                float l0 = v[0] - __bfloat162float(hh.x);
                float l1 = v[1] - __bfloat162float(hh.y);
                __nv_bfloat162 ll = __floats2bfloat162_rn(l0, l1);
                uint32_t so = sw128(rowbase + q * 4);
                *(uint32_t*)(smem + OFF_B + (buf*2 + 0) * 8192 + so) = *(uint32_t*)&hh;
                *(uint32_t*)(smem + OFF_B + (buf*2 + 1) * 8192 + so) = *(uint32_t*)&ll;
            }
        }
    };

    const uint32_t aOff = (uint32_t)((m0w + (lid & 15)) * 128 + (lid >> 4) * 16);
    const uint32_t bOff = (uint32_t)((n0w + (lid & 7) + ((lid >> 4) & 1) * 8) * 128 + ((lid >> 3) & 1) * 16);

    // prologue
    loadA_async(0, 0);
    if (MODE == 1) gatherB_def(0, 0); else gatherB_conv(0, 0);
    asm volatile("cp.async.wait_group 0;");
    __syncthreads();

    for (int c = 0; c < NC; c++) {
        const int buf = c & 1;
        if (c + 1 < NC) {
            loadA_async(c + 1, buf ^ 1);
            if (MODE == 1) gatherB_def(c + 1, buf ^ 1); else gatherB_conv(c + 1, buf ^ 1);
        }

        const uint32_t sAh = sb + OFF_A + (buf*2 + 0) * 16384;
        const uint32_t sAl = sb + OFF_A + (buf*2 + 1) * 16384;
        const uint32_t sBh = sb + OFF_B + (buf*2 + 0) * 8192;
        const uint32_t sBl = sb + OFF_B + (buf*2 + 1) * 8192;

#pragma unroll
        for (int ks = 0; ks < 4; ks++) {
            uint32_t ah[2][4], al[2][4], bh[2][4], bl[2][4];
#pragma unroll
            for (int i = 0; i < 2; i++) {
                ldsm4(ah[i], sAh + sw128(aOff + (uint32_t)(i * 2048 + ks * 32)));
                ldsm4(al[i], sAl + sw128(aOff + (uint32_t)(i * 2048 + ks * 32)));
            }
#pragma unroll
            for (int j = 0; j < 2; j++) {
                ldsm4(bh[j], sBh + sw128(bOff + (uint32_t)(j * 2048 + ks * 32)));
                ldsm4(bl[j], sBl + sw128(bOff + (uint32_t)(j * 2048 + ks * 32)));
            }
#pragma unroll
            for (int i = 0; i < 2; i++)
#pragma unroll
                for (int jn = 0; jn < 4; jn++) {
                    int jp = jn >> 1, sel = (jn & 1) * 2;
                    mma16816(acc[i][jn], ah[i], bh[jp][sel], bh[jp][sel + 1]);
                    mma16816(acc[i][jn], ah[i], bl[jp][sel], bl[jp][sel + 1]);
                    mma16816(acc[i][jn], al[i], bh[jp][sel], bh[jp][sel + 1]);
                }
        }
        if (c + 1 < NC) asm volatile("cp.async.wait_group 0;");
        __syncthreads();
    }

    // ---- epilogue ----
#pragma unroll
    for (int i = 0; i < 2; i++) {
        int row0 = m0 + m0w + i * 16 + (lid >> 2);
#pragma unroll
        for (int half = 0; half < 2; half++) {
            int co = row0 + half * 8;
            if (co >= Cout) continue;
            float bv = bias[co];
            size_t rbase = ((size_t)b * Cout + co) * HWOUT + hw0 + n0w + (lid & 3) * 2;
#pragma unroll
            for (int jn = 0; jn < 4; jn++) {
                float v0 = acc[i][jn][half * 2 + 0] + bv;
                float v1 = acc[i][jn][half * 2 + 1] + bv;
                size_t o = rbase + jn * 8;
                if (EPI == 1) {
                    float2 s = *(const float2*)(epi_src + o);
                    v0 = fmaxf(v0, 0.f) + s.x; v1 = fmaxf(v1, 0.f) + s.y;
                } else if (EPI == 2) {
                    float2 s = *(const float2*)(epi_src + o);
                    v0 += s.x; v1 += s.y;
                }
                *(float2*)(out + o) = make_float2(v0, v1);
            }
        }
    }
}

extern "C" void kernel_launch(void* const* d_in, const int* in_sizes, int n_in,
                              void* d_out, int out_size)
{
    const float* f0 = (const float*)d_in[0];
    const float* f1 = (const float*)d_in[1];
    const float* f2 = (const float*)d_in[2];
    const float* com_w[2] = {(const float*)d_in[3], (const float*)d_in[5]};
    const float* com_b[2] = {(const float*)d_in[4], (const float*)d_in[6]};
    const float* dcn_w[2] = {(const float*)d_in[7], (const float*)d_in[9]};
    const float* dcn_b[2] = {(const float*)d_in[8], (const float*)d_in[10]};
    const float* res_w = (const float*)d_in[11];
    const float* res_b = (const float*)d_in[12];
    float* out = (float*)d_out;

    float *gf, *gom;
    __nv_bfloat16 *wdef, *wcom, *wres;
    cudaGetSymbolAddress((void**)&gf,   g_f);
    cudaGetSymbolAddress((void**)&gom,  g_om);
    cudaGetSymbolAddress((void**)&wdef, g_wdef);
    cudaGetSymbolAddress((void**)&wcom, g_wcom);
    cudaGetSymbolAddress((void**)&wres, g_wres);

    cudaFuncSetAttribute(tc_gemm<0,0>, cudaFuncAttributeMaxDynamicSharedMemorySize, SMEM_DEF);
    cudaFuncSetAttribute(tc_gemm<1,1>, cudaFuncAttributeMaxDynamicSharedMemorySize, SMEM_DEF);
    cudaFuncSetAttribute(tc_gemm<0,2>, cudaFuncAttributeMaxDynamicSharedMemorySize, SMEM_DEF);

    cudaMemcpyAsync(gf, f2, sizeof(float) * BATCH * CIN * HWOUT, cudaMemcpyDeviceToDevice);

    const int nd = 256 * KDEF;
    const int nc = 128 * KCONV;
    const int nr = 256 * KCONV;
    for (int l = 0; l < 2; l++) {
        prep_w<<<(nd + 255) / 256, 256>>>(dcn_w[l], wdef + (size_t)l*2*nd, wdef + (size_t)l*2*nd + nd, 256, 256, KDEF);
        prep_w<<<(nc + 255) / 256, 256>>>(com_w[l], wcom + (size_t)l*2*nc, wcom + (size_t)l*2*nc + nc,  48, 128, KCONV);
    }
    prep_w<<<(nr + 255) / 256, 256>>>(res_w, wres, wres + nr, 256, 256, KCONV);

    const float* feats[2] = {f1, f0};
    const int Hins[2]    = {80, 160};
    const int strides[2] = {2, 4};
    const int pads[2]    = {1, 3};
    const int dils[2]    = {1, 3};

    for (int rep = 0; rep < 2; rep++) {
        for (int l = 0; l < 2; l++) {
            tc_gemm<0,0><<<dim3(100, 1), NTHREADS, SMEM_CONV>>>(
                gf, 40, 40,
                wcom + (size_t)l*2*nc, wcom + (size_t)l*2*nc + nc,
                com_b[l], nullptr, nullptr, gom, 48, KCONV, 1, 1, 1);
            tc_gemm<1,1><<<dim3(100, 2), NTHREADS, SMEM_DEF>>>(
                feats[l], Hins[l], Hins[l],
                wdef + (size_t)l*2*nd, wdef + (size_t)l*2*nd + nd,
                dcn_b[l], gom, gf, gf, 256, KDEF, strides[l], pads[l], dils[l]);
        }
    }
    tc_gemm<0,2><<<dim3(100, 2), NTHREADS, SMEM_CONV>>>(
        gf, 40, 40, wres, wres + nr, res_b, nullptr, f2, out, 256, KCONV, 1, 1, 1);
}

// round 6
// speedup vs baseline: 1.7769x; 1.0476x over previous
#include <cuda_runtime.h>
#include <cuda_bf16.h>
#include <math.h>
#include <stdint.h>

#define WOUT 40
#define HWOUT 1600
#define CIN 256
#define BATCH 4

#define BN 64
#define KC 64
#define NTHREADS 512
#define KDEF (CIN*16)
#define KCONV (CIN*9)

// ---------------- device scratch ----------------
__device__ float g_f[BATCH*CIN*HWOUT];
__device__ float g_om[BATCH*48*HWOUT];
__device__ __align__(16) __nv_bfloat16 g_wdef[2*2*256*KDEF];
__device__ __align__(16) __nv_bfloat16 g_wcom[2*2*64*KCONV];
__device__ __align__(16) __nv_bfloat16 g_wres[2*256*KCONV];

__device__ __forceinline__ uint32_t smem_u32(const void* p) {
    uint32_t a;
    asm("{ .reg .u64 t; cvta.to.shared.u64 t, %1; cvt.u32.u64 %0, t; }" : "=r"(a) : "l"(p));
    return a;
}
__device__ __forceinline__ uint32_t sw128(uint32_t o) { return o ^ ((o >> 3) & 0x70); }

__device__ __forceinline__ void ldsm4(uint32_t* r, uint32_t addr) {
    asm volatile("ldmatrix.sync.aligned.m8n8.x4.shared.b16 {%0,%1,%2,%3}, [%4];"
        : "=r"(r[0]), "=r"(r[1]), "=r"(r[2]), "=r"(r[3]) : "r"(addr));
}
__device__ __forceinline__ void mma16816(float* c, const uint32_t* a, uint32_t b0, uint32_t b1) {
    asm volatile("mma.sync.aligned.m16n8k16.row.col.f32.bf16.bf16.f32 "
        "{%0,%1,%2,%3},{%4,%5,%6,%7},{%8,%9},{%0,%1,%2,%3};"
        : "+f"(c[0]), "+f"(c[1]), "+f"(c[2]), "+f"(c[3])
        : "r"(a[0]), "r"(a[1]), "r"(a[2]), "r"(a[3]), "r"(b0), "r"(b1));
}

__global__ void prep_w(const float* __restrict__ w, __nv_bfloat16* __restrict__ hi,
                       __nv_bfloat16* __restrict__ lo, int Cout, int Mpad, int Ktot)
{
    int i = blockIdx.x * blockDim.x + threadIdx.x;
    if (i >= Mpad * Ktot) return;
    int row = i / Ktot;
    float v = (row < Cout) ? w[i] : 0.f;
    __nv_bfloat16 h = __float2bfloat16(v);
    hi[i] = h;
    lo[i] = __float2bfloat16(v - __bfloat162float(h));
}

// MODE 0: implicit-GEMM 3x3 conv (s1 p1).  MODE 1: modulated deformable conv (k=4, K=16).
// EPI 0: +bias ; 1: relu(v+bias)+epi_src ; 2: v+bias+epi_src
// MT: m-tiles per warp (BM = MT*64)
template<int MODE, int EPI, int MT>
__global__ void __launch_bounds__(NTHREADS)
tc_gemm(const float* __restrict__ x, int Hin, int Win,
        const __nv_bfloat16* __restrict__ whi, const __nv_bfloat16* __restrict__ wlo,
        const float* __restrict__ bias, const float* __restrict__ om,
        const float* __restrict__ epi_src, float* __restrict__ out,
        int Cout, int Ktot, int stride, int pad, int dil)
{
    constexpr int BM = MT * 64;
    constexpr int ABUF = BM * 128;        // bytes per A (buf,fmt) tile
    constexpr int OFF_B = 4 * ABUF;
    constexpr int OFF_META = OFF_B + 32768;

    extern __shared__ __align__(1024) char smem[];
    const uint32_t sb = smem_u32(smem);
    const int tid = threadIdx.x;
    const int wid = tid >> 5, lid = tid & 31;
    const int n0 = blockIdx.x * BN;
    const int m0 = blockIdx.y * BM;
    const int b  = n0 / HWOUT;
    const int hw0 = n0 - b * HWOUT;
    const int HWin = Hin * Win;
    const float* xb = x + (size_t)b * CIN * HWin;

    int2*   mAD = (int2*)  (smem + OFF_META);
    float4* mW  = (float4*)(smem + OFF_META + 8192);

    // ---- per-CTA sampling metadata: clamped pair-base addr + folded weights ----
    if (MODE == 1) {
        const float* omb = om + (size_t)b * 48 * HWOUT;
        for (int i = tid; i < 1024; i += NTHREADS) {   // 16 taps x 64 px
            int k = i >> 6, nn = i & 63;
            int hw = hw0 + nn;
            int h = hw / WOUT, w = hw - h * WOUT;
            float dy = omb[(size_t)(2*k  )*HWOUT + hw];
            float dx = omb[(size_t)(2*k+1)*HWOUT + hw];
            float mm = omb[(size_t)(32+k )*HWOUT + hw];
            mm = 1.0f / (1.0f + expf(-mm));
            float py = (float)((k >> 2) * dil + h * stride - pad) + dy;
            float px = (float)((k &  3) * dil + w * stride - pad) + dx;
            float fy = floorf(py), fx = floorf(px);
            int y0 = (int)fy, x0 = (int)fx;
            int y1 = y0 + 1, x1 = x0 + 1;
            float ly = py - fy, lx = px - fx;
            float wy0 = ((y0 >= 0) & (y0 < Hin)) ? (1.f - ly) * mm : 0.f;
            float wy1 = ((y1 >= 0) & (y1 < Hin)) ? ly * mm : 0.f;
            float wx0 = ((x0 >= 0) & (x0 < Win)) ? (1.f - lx) : 0.f;
            float wx1 = ((x1 >= 0) & (x1 < Win)) ? lx : 0.f;
            int xL = min(max(x0, 0), Win - 2);
            float wL = (x0 == xL ? wx0 : 0.f) + (x1 == xL ? wx1 : 0.f);
            float wR = (x0 == xL + 1 ? wx0 : 0.f) + (x1 == xL + 1 ? wx1 : 0.f);
            int yT = min(max(y0, 0), Hin - 1);
            int yB = min(max(y1, 0), Hin - 1);
            mAD[i] = make_int2(yT * Win + xL, (yB - yT) * Win);
            mW[i]  = make_float4(wy0 * wL, wy0 * wR, wy1 * wL, wy1 * wR);
        }
        __syncthreads();
    }

    float acc[MT][2][4];
#pragma unroll
    for (int i = 0; i < MT; i++)
#pragma unroll
        for (int j = 0; j < 2; j++)
#pragma unroll
            for (int q = 0; q < 4; q++) acc[i][j][q] = 0.f;

    const int NC = Ktot / KC;
    const int wm = wid & 3, wn = wid >> 2;
    const int m0w = wm * (MT * 16);
    const int n0w = wn * 16;

    auto loadA_async = [&](int c, int buf) {
        const int k0 = c * KC;
        constexpr int TOT = BM * 16;      // cp.async count (2 fmt x BM x 8)
#pragma unroll
        for (int s = 0; s < TOT / NTHREADS; s++) {
            int f = tid + s * NTHREADS;
            int fmt = f / (BM * 8);
            int rem = f - fmt * (BM * 8);
            int r = rem >> 3, j = rem & 7;
            const __nv_bfloat16* src = fmt ? wlo : whi;
            uint32_t dst = sb + (uint32_t)((buf*2 + fmt) * ABUF) + sw128((uint32_t)(r*128 + j*16));
            const void* gsrc = src + (size_t)(m0 + r) * Ktot + k0 + j * 8;
            asm volatile("cp.async.cg.shared.global [%0], [%1], 16;" :: "r"(dst), "l"(gsrc));
        }
        asm volatile("cp.async.commit_group;");
    };

    const int pxT = tid & 63;            // this thread's pixel
    const int grpT = tid >> 6;           // 0..7: tap-pair (deform) or k-group (conv)
    const uint32_t xorv = (uint32_t)((pxT & 7) << 4);
    const uint32_t rowb = (uint32_t)(pxT * 128);

    // deform B gather: thread = (px, tap-pair), loops 4 channels
    auto gatherB_def = [&](int c, int buf) {
        int2 ad0 = mAD[(2*grpT  ) * 64 + pxT];
        int2 ad1 = mAD[(2*grpT+1) * 64 + pxT];
        float4 w0 = mW[(2*grpT  ) * 64 + pxT];
        float4 w1 = mW[(2*grpT+1) * 64 + pxT];
#pragma unroll
        for (int ciL = 0; ciL < 4; ciL++) {
            const float* plane = xb + (size_t)(c * 4 + ciL) * HWin;
            const float* p0 = plane + ad0.x;
            const float* p1 = plane + ad1.x;
            float v0 = w0.x*p0[0] + w0.y*p0[1] + w0.z*p0[ad0.y] + w0.w*p0[ad0.y+1];
            float v1 = w1.x*p1[0] + w1.y*p1[1] + w1.z*p1[ad1.y] + w1.w*p1[ad1.y+1];
            __nv_bfloat162 hh = __floats2bfloat162_rn(v0, v1);
            float l0 = v0 - __bfloat162float(hh.x);
            float l1 = v1 - __bfloat162float(hh.y);
            __nv_bfloat162 ll = __floats2bfloat162_rn(l0, l1);
            // full in-row offset XORed once (bug fixed: no add after xor)
            uint32_t so = rowb + (((uint32_t)(ciL * 32 + grpT * 4)) ^ xorv);
            *(uint32_t*)(smem + OFF_B + (buf*2 + 0) * 8192 + so) = *(uint32_t*)&hh;
            *(uint32_t*)(smem + OFF_B + (buf*2 + 1) * 8192 + so) = *(uint32_t*)&ll;
        }
    };

    // conv B gather: thread = (px, k-group of 8)
    auto gatherB_conv = [&](int c, int buf) {
        int hw = hw0 + pxT;
        int h = hw / WOUT, w_ = hw - h * WOUT;
#pragma unroll
        for (int q = 0; q < 4; q++) {
            float v[2];
#pragma unroll
            for (int u = 0; u < 2; u++) {
                int k = c * KC + grpT * 8 + q * 2 + u;
                int ci = k / 9, jj = k - ci * 9;
                int y  = h + jj / 3 - 1;
                int xx = w_ + (jj - (jj / 3) * 3) - 1;
                v[u] = (y >= 0 && y < Hin && xx >= 0 && xx < Win)
                     ? xb[(size_t)ci * HWin + y * Win + xx] : 0.f;
            }
            __nv_bfloat162 hh = __floats2bfloat162_rn(v[0], v[1]);
            float l0 = v[0] - __bfloat162float(hh.x);
            float l1 = v[1] - __bfloat162float(hh.y);
            __nv_bfloat162 ll = __floats2bfloat162_rn(l0, l1);
            uint32_t so = rowb + (((uint32_t)(grpT * 16 + q * 4)) ^ xorv);
            *(uint32_t*)(smem + OFF_B + (buf*2 + 0) * 8192 + so) = *(uint32_t*)&hh;
            *(uint32_t*)(smem + OFF_B + (buf*2 + 1) * 8192 + so) = *(uint32_t*)&ll;
        }
    };

    const uint32_t aOff = (uint32_t)((m0w + (lid & 15)) * 128 + (lid >> 4) * 16);
    const uint32_t bOff = (uint32_t)((n0w + (lid & 7) + ((lid >> 4) & 1) * 8) * 128 + ((lid >> 3) & 1) * 16);

    // prologue
    loadA_async(0, 0);
    if (MODE == 1) gatherB_def(0, 0); else gatherB_conv(0, 0);
    asm volatile("cp.async.wait_group 0;");
    __syncthreads();

    for (int c = 0; c < NC; c++) {
        const int buf = c & 1;
        if (c + 1 < NC) {
            loadA_async(c + 1, buf ^ 1);
            if (MODE == 1) gatherB_def(c + 1, buf ^ 1); else gatherB_conv(c + 1, buf ^ 1);
        }

        const uint32_t sAh = sb + (uint32_t)((buf*2 + 0) * ABUF);
        const uint32_t sAl = sb + (uint32_t)((buf*2 + 1) * ABUF);
        const uint32_t sBh = sb + OFF_B + (buf*2 + 0) * 8192;
        const uint32_t sBl = sb + OFF_B + (buf*2 + 1) * 8192;

#pragma unroll
        for (int ks = 0; ks < 4; ks++) {
            uint32_t ah[MT][4], al[MT][4], bh[4], bl[4];
#pragma unroll
            for (int i = 0; i < MT; i++) {
                ldsm4(ah[i], sAh + sw128(aOff + (uint32_t)(i * 2048 + ks * 32)));
                ldsm4(al[i], sAl + sw128(aOff + (uint32_t)(i * 2048 + ks * 32)));
            }
            ldsm4(bh, sBh + sw128(bOff + (uint32_t)(ks * 32)));
            ldsm4(bl, sBl + sw128(bOff + (uint32_t)(ks * 32)));
#pragma unroll
            for (int i = 0; i < MT; i++)
#pragma unroll
                for (int jn = 0; jn < 2; jn++) {
                    int sel = jn * 2;
                    mma16816(acc[i][jn], ah[i], bh[sel], bh[sel + 1]);
                    mma16816(acc[i][jn], ah[i], bl[sel], bl[sel + 1]);
                    mma16816(acc[i][jn], al[i], bh[sel], bh[sel + 1]);
                }
        }
        if (c + 1 < NC) asm volatile("cp.async.wait_group 0;");
        __syncthreads();
    }

    // ---- epilogue ----
#pragma unroll
    for (int i = 0; i < MT; i++) {
        int row0 = m0 + m0w + i * 16 + (lid >> 2);
#pragma unroll
        for (int half = 0; half < 2; half++) {
            int co = row0 + half * 8;
            if (co >= Cout) continue;
            float bv = bias[co];
            size_t rbase = ((size_t)b * Cout + co) * HWOUT + hw0 + n0w + (lid & 3) * 2;
#pragma unroll
            for (int jn = 0; jn < 2; jn++) {
                float v0 = acc[i][jn][half * 2 + 0] + bv;
                float v1 = acc[i][jn][half * 2 + 1] + bv;
                size_t o = rbase + jn * 8;
                if (EPI == 1) {
                    float2 s = *(const float2*)(epi_src + o);
                    v0 = fmaxf(v0, 0.f) + s.x; v1 = fmaxf(v1, 0.f) + s.y;
                } else if (EPI == 2) {
                    float2 s = *(const float2*)(epi_src + o);
                    v0 += s.x; v1 += s.y;
                }
                *(float2*)(out + o) = make_float2(v0, v1);
            }
        }
    }
}

#define SMEM_DEF  (4*128*128 + 32768 + 24576)   // 122880
#define SMEM_RES  (4*128*128 + 32768)           // 98304
#define SMEM_COM  (4*64*128 + 32768)            // 65536

extern "C" void kernel_launch(void* const* d_in, const int* in_sizes, int n_in,
                              void* d_out, int out_size)
{
    const float* f0 = (const float*)d_in[0];
    const float* f1 = (const float*)d_in[1];
    const float* f2 = (const float*)d_in[2];
    const float* com_w[2] = {(const float*)d_in[3], (const float*)d_in[5]};
    const float* com_b[2] = {(const float*)d_in[4], (const float*)d_in[6]};
    const float* dcn_w[2] = {(const float*)d_in[7], (const float*)d_in[9]};
    const float* dcn_b[2] = {(const float*)d_in[8], (const float*)d_in[10]};
    const float* res_w = (const float*)d_in[11];
    const float* res_b = (const float*)d_in[12];
    float* out = (float*)d_out;

    float *gf, *gom;
    __nv_bfloat16 *wdef, *wcom, *wres;
    cudaGetSymbolAddress((void**)&gf,   g_f);
    cudaGetSymbolAddress((void**)&gom,  g_om);
    cudaGetSymbolAddress((void**)&wdef, g_wdef);
    cudaGetSymbolAddress((void**)&wcom, g_wcom);
    cudaGetSymbolAddress((void**)&wres, g_wres);

    cudaFuncSetAttribute(tc_gemm<0,0,1>, cudaFuncAttributeMaxDynamicSharedMemorySize, SMEM_COM);
    cudaFuncSetAttribute(tc_gemm<1,1,2>, cudaFuncAttributeMaxDynamicSharedMemorySize, SMEM_DEF);
    cudaFuncSetAttribute(tc_gemm<0,2,2>, cudaFuncAttributeMaxDynamicSharedMemorySize, SMEM_RES);

    cudaMemcpyAsync(gf, f2, sizeof(float) * BATCH * CIN * HWOUT, cudaMemcpyDeviceToDevice);

    const int nd = 256 * KDEF;
    const int nc = 64 * KCONV;
    const int nr = 256 * KCONV;
    for (int l = 0; l < 2; l++) {
        prep_w<<<(nd + 255) / 256, 256>>>(dcn_w[l], wdef + (size_t)l*2*nd, wdef + (size_t)l*2*nd + nd, 256, 256, KDEF);
        prep_w<<<(nc + 255) / 256, 256>>>(com_w[l], wcom + (size_t)l*2*nc, wcom + (size_t)l*2*nc + nc,  48, 64, KCONV);
    }
    prep_w<<<(nr + 255) / 256, 256>>>(res_w, wres, wres + nr, 256, 256, KCONV);

    const float* feats[2] = {f1, f0};
    const int Hins[2]    = {80, 160};
    const int strides[2] = {2, 4};
    const int pads[2]    = {1, 3};
    const int dils[2]    = {1, 3};

    for (int rep = 0; rep < 2; rep++) {
        for (int l = 0; l < 2; l++) {
            tc_gemm<0,0,1><<<dim3(100, 1), NTHREADS, SMEM_COM>>>(
                gf, 40, 40,
                wcom + (size_t)l*2*nc, wcom + (size_t)l*2*nc + nc,
                com_b[l], nullptr, nullptr, gom, 48, KCONV, 1, 1, 1);
            tc_gemm<1,1,2><<<dim3(100, 2), NTHREADS, SMEM_DEF>>>(
                feats[l], Hins[l], Hins[l],
                wdef + (size_t)l*2*nd, wdef + (size_t)l*2*nd + nd,
                dcn_b[l], gom, gf, gf, 256, KDEF, strides[l], pads[l], dils[l]);
        }
    }
    tc_gemm<0,2,2><<<dim3(100, 2), NTHREADS, SMEM_RES>>>(
        gf, 40, 40, wres, wres + nr, res_b, nullptr, f2, out, 256, KCONV, 1, 1, 1);
}

// round 7
// speedup vs baseline: 2.2292x; 1.2545x over previous
#include <cuda_runtime.h>
#include <cuda_bf16.h>
#include <math.h>
#include <stdint.h>

#define WOUT 40
#define HWOUT 1600
#define CIN 256
#define BATCH 4

#define BN 64
#define KC 64
#define NTHREADS 512
#define KDEF (CIN*16)
#define KCONV (CIN*9)

// ---------------- device scratch ----------------
__device__ float g_f[BATCH*CIN*HWOUT];
__device__ float g_om[BATCH*48*HWOUT];
__device__ __align__(16) __nv_bfloat16 g_wdef[2*2*256*KDEF];
__device__ __align__(16) __nv_bfloat16 g_wcom[2*2*64*KCONV];
__device__ __align__(16) __nv_bfloat16 g_wres[2*256*KCONV];

__device__ __forceinline__ uint32_t smem_u32(const void* p) {
    uint32_t a;
    asm("{ .reg .u64 t; cvta.to.shared.u64 t, %1; cvt.u32.u64 %0, t; }" : "=r"(a) : "l"(p));
    return a;
}
__device__ __forceinline__ uint32_t sw128(uint32_t o) { return o ^ ((o >> 3) & 0x70); }

__device__ __forceinline__ void ldsm4(uint32_t* r, uint32_t addr) {
    asm volatile("ldmatrix.sync.aligned.m8n8.x4.shared.b16 {%0,%1,%2,%3}, [%4];"
        : "=r"(r[0]), "=r"(r[1]), "=r"(r[2]), "=r"(r[3]) : "r"(addr));
}
__device__ __forceinline__ void mma16816(float* c, const uint32_t* a, uint32_t b0, uint32_t b1) {
    asm volatile("mma.sync.aligned.m16n8k16.row.col.f32.bf16.bf16.f32 "
        "{%0,%1,%2,%3},{%4,%5,%6,%7},{%8,%9},{%0,%1,%2,%3};"
        : "+f"(c[0]), "+f"(c[1]), "+f"(c[2]), "+f"(c[3])
        : "r"(a[0]), "r"(a[1]), "r"(a[2]), "r"(a[3]), "r"(b0), "r"(b1));
}

__global__ void prep_w(const float* __restrict__ w, __nv_bfloat16* __restrict__ hi,
                       __nv_bfloat16* __restrict__ lo, int Cout, int Mpad, int Ktot)
{
    int i = blockIdx.x * blockDim.x + threadIdx.x;
    if (i >= Mpad * Ktot) return;
    int row = i / Ktot;
    float v = (row < Cout) ? w[i] : 0.f;
    __nv_bfloat16 h = __float2bfloat16(v);
    hi[i] = h;
    lo[i] = __float2bfloat16(v - __bfloat162float(h));
}

// MODE 0: implicit-GEMM 3x3 conv (s1 p1).  MODE 1: modulated deformable conv (k=4, K=16).
// EPI 0: +bias ; 1: relu(v+bias)+epi_src ; 2: v+bias+epi_src
// MT: m-tiles per warp (BM = MT*64); warp tile = (MT*16) x 16
template<int MODE, int EPI, int MT>
__global__ void __launch_bounds__(NTHREADS)
tc_gemm(const float* __restrict__ x, int Hin, int Win,
        const __nv_bfloat16* __restrict__ whi, const __nv_bfloat16* __restrict__ wlo,
        const float* __restrict__ bias, const float* __restrict__ om,
        const float* __restrict__ epi_src, float* __restrict__ out,
        int Cout, int Ktot, int stride, int pad, int dil)
{
    constexpr int BM = MT * 64;
    constexpr int ABUF = BM * 128;        // bytes per A (buf,fmt) tile
    constexpr int OFF_B = 4 * ABUF;
    constexpr int OFF_META = OFF_B + 32768;

    extern __shared__ __align__(1024) char smem[];
    const uint32_t sb = smem_u32(smem);
    const int tid = threadIdx.x;
    const int wid = tid >> 5, lid = tid & 31;
    const int n0 = blockIdx.x * BN;
    const int m0 = blockIdx.y * BM;
    const int b  = n0 / HWOUT;
    const int hw0 = n0 - b * HWOUT;
    const int HWin = Hin * Win;
    const float* xb = x + (size_t)b * CIN * HWin;

    int2*   mAD = (int2*)  (smem + OFF_META);
    float4* mW  = (float4*)(smem + OFF_META + 8192);

    // ---- per-CTA sampling metadata: clamped pair-base addr + folded weights ----
    if (MODE == 1) {
        const float* omb = om + (size_t)b * 48 * HWOUT;
        for (int i = tid; i < 1024; i += NTHREADS) {   // 16 taps x 64 px
            int k = i >> 6, nn = i & 63;
            int hw = hw0 + nn;
            int h = hw / WOUT, w = hw - h * WOUT;
            float dy = omb[(size_t)(2*k  )*HWOUT + hw];
            float dx = omb[(size_t)(2*k+1)*HWOUT + hw];
            float mm = omb[(size_t)(32+k )*HWOUT + hw];
            mm = 1.0f / (1.0f + expf(-mm));
            float py = (float)((k >> 2) * dil + h * stride - pad) + dy;
            float px = (float)((k &  3) * dil + w * stride - pad) + dx;
            float fy = floorf(py), fx = floorf(px);
            int y0 = (int)fy, x0 = (int)fx;
            int y1 = y0 + 1, x1 = x0 + 1;
            float ly = py - fy, lx = px - fx;
            float wy0 = ((y0 >= 0) & (y0 < Hin)) ? (1.f - ly) * mm : 0.f;
            float wy1 = ((y1 >= 0) & (y1 < Hin)) ? ly * mm : 0.f;
            float wx0 = ((x0 >= 0) & (x0 < Win)) ? (1.f - lx) : 0.f;
            float wx1 = ((x1 >= 0) & (x1 < Win)) ? lx : 0.f;
            int xL = min(max(x0, 0), Win - 2);
            float wL = (x0 == xL ? wx0 : 0.f) + (x1 == xL ? wx1 : 0.f);
            float wR = (x0 == xL + 1 ? wx0 : 0.f) + (x1 == xL + 1 ? wx1 : 0.f);
            int yT = min(max(y0, 0), Hin - 1);
            int yB = min(max(y1, 0), Hin - 1);
            mAD[i] = make_int2(yT * Win + xL, (yB - yT) * Win);
            mW[i]  = make_float4(wy0 * wL, wy0 * wR, wy1 * wL, wy1 * wR);
        }
        __syncthreads();
    }

    float acc[MT][2][4];
#pragma unroll
    for (int i = 0; i < MT; i++)
#pragma unroll
        for (int j = 0; j < 2; j++)
#pragma unroll
            for (int q = 0; q < 4; q++) acc[i][j][q] = 0.f;

    const int NC = Ktot / KC;
    const int wm = wid & 3, wn = wid >> 2;
    const int m0w = wm * (MT * 16);
    const int n0w = wn * 16;

    auto loadA_async = [&](int c, int buf) {
        const int k0 = c * KC;
        constexpr int TOT = BM * 16;      // cp.async count (2 fmt x BM x 8)
#pragma unroll
        for (int s = 0; s < TOT / NTHREADS; s++) {
            int f = tid + s * NTHREADS;
            int fmt = f / (BM * 8);
            int rem = f - fmt * (BM * 8);
            int r = rem >> 3, j = rem & 7;
            const __nv_bfloat16* src = fmt ? wlo : whi;
            uint32_t dst = sb + (uint32_t)((buf*2 + fmt) * ABUF) + sw128((uint32_t)(r*128 + j*16));
            const void* gsrc = src + (size_t)(m0 + r) * Ktot + k0 + j * 8;
            asm volatile("cp.async.cg.shared.global [%0], [%1], 16;" :: "r"(dst), "l"(gsrc));
        }
        asm volatile("cp.async.commit_group;");
    };

    const int pxT = tid & 63;            // this thread's pixel
    const int grpT = tid >> 6;           // 0..7: tap-pair (deform) or k-group (conv)
    const uint32_t xorv = (uint32_t)((pxT & 7) << 4);
    const uint32_t rowb = (uint32_t)(pxT * 128);

    // deform B gather: thread = (px, tap-pair), loops 4 channels
    auto gatherB_def = [&](int c, int buf) {
        int2 ad0 = mAD[(2*grpT  ) * 64 + pxT];
        int2 ad1 = mAD[(2*grpT+1) * 64 + pxT];
        float4 w0 = mW[(2*grpT  ) * 64 + pxT];
        float4 w1 = mW[(2*grpT+1) * 64 + pxT];
#pragma unroll
        for (int ciL = 0; ciL < 4; ciL++) {
            const float* plane = xb + (size_t)(c * 4 + ciL) * HWin;
            const float* p0 = plane + ad0.x;
            const float* p1 = plane + ad1.x;
            float v0 = w0.x*p0[0] + w0.y*p0[1] + w0.z*p0[ad0.y] + w0.w*p0[ad0.y+1];
            float v1 = w1.x*p1[0] + w1.y*p1[1] + w1.z*p1[ad1.y] + w1.w*p1[ad1.y+1];
            __nv_bfloat162 hh = __floats2bfloat162_rn(v0, v1);
            float l0 = v0 - __bfloat162float(hh.x);
            float l1 = v1 - __bfloat162float(hh.y);
            __nv_bfloat162 ll = __floats2bfloat162_rn(l0, l1);
            uint32_t so = rowb + (((uint32_t)(ciL * 32 + grpT * 4)) ^ xorv);
            *(uint32_t*)(smem + OFF_B + (buf*2 + 0) * 8192 + so) = *(uint32_t*)&hh;
            *(uint32_t*)(smem + OFF_B + (buf*2 + 1) * 8192 + so) = *(uint32_t*)&ll;
        }
    };

    // conv B gather: thread = (px, k-group of 8)
    auto gatherB_conv = [&](int c, int buf) {
        int hw = hw0 + pxT;
        int h = hw / WOUT, w_ = hw - h * WOUT;
#pragma unroll
        for (int q = 0; q < 4; q++) {
            float v[2];
#pragma unroll
            for (int u = 0; u < 2; u++) {
                int k = c * KC + grpT * 8 + q * 2 + u;
                int ci = k / 9, jj = k - ci * 9;
                int y  = h + jj / 3 - 1;
                int xx = w_ + (jj - (jj / 3) * 3) - 1;
                v[u] = (y >= 0 && y < Hin && xx >= 0 && xx < Win)
                     ? xb[(size_t)ci * HWin + y * Win + xx] : 0.f;
            }
            __nv_bfloat162 hh = __floats2bfloat162_rn(v[0], v[1]);
            float l0 = v[0] - __bfloat162float(hh.x);
            float l1 = v[1] - __bfloat162float(hh.y);
            __nv_bfloat162 ll = __floats2bfloat162_rn(l0, l1);
            uint32_t so = rowb + (((uint32_t)(grpT * 16 + q * 4)) ^ xorv);
            *(uint32_t*)(smem + OFF_B + (buf*2 + 0) * 8192 + so) = *(uint32_t*)&hh;
            *(uint32_t*)(smem + OFF_B + (buf*2 + 1) * 8192 + so) = *(uint32_t*)&ll;
        }
    };

    const uint32_t aOff = (uint32_t)((m0w + (lid & 15)) * 128 + (lid >> 4) * 16);
    const uint32_t bOff = (uint32_t)((n0w + (lid & 7) + ((lid >> 4) & 1) * 8) * 128 + ((lid >> 3) & 1) * 16);

    // prologue
    loadA_async(0, 0);
    if (MODE == 1) gatherB_def(0, 0); else gatherB_conv(0, 0);
    asm volatile("cp.async.wait_group 0;");
    __syncthreads();

    for (int c = 0; c < NC; c++) {
        const int buf = c & 1;
        if (c + 1 < NC) {
            loadA_async(c + 1, buf ^ 1);
            if (MODE == 1) gatherB_def(c + 1, buf ^ 1); else gatherB_conv(c + 1, buf ^ 1);
        }

        const uint32_t sAh = sb + (uint32_t)((buf*2 + 0) * ABUF);
        const uint32_t sAl = sb + (uint32_t)((buf*2 + 1) * ABUF);
        const uint32_t sBh = sb + OFF_B + (buf*2 + 0) * 8192;
        const uint32_t sBl = sb + OFF_B + (buf*2 + 1) * 8192;

#pragma unroll
        for (int ks = 0; ks < 4; ks++) {
            uint32_t ah[MT][4], al[MT][4], bh[4], bl[4];
#pragma unroll
            for (int i = 0; i < MT; i++) {
                ldsm4(ah[i], sAh + sw128(aOff + (uint32_t)(i * 2048 + ks * 32)));
                ldsm4(al[i], sAl + sw128(aOff + (uint32_t)(i * 2048 + ks * 32)));
            }
            ldsm4(bh, sBh + sw128(bOff + (uint32_t)(ks * 32)));
            ldsm4(bl, sBl + sw128(bOff + (uint32_t)(ks * 32)));
#pragma unroll
            for (int i = 0; i < MT; i++)
#pragma unroll
                for (int jn = 0; jn < 2; jn++) {
                    int sel = jn * 2;
                    mma16816(acc[i][jn], ah[i], bh[sel], bh[sel + 1]);
                    mma16816(acc[i][jn], ah[i], bl[sel], bl[sel + 1]);
                    mma16816(acc[i][jn], al[i], bh[sel], bh[sel + 1]);
                }
        }
        if (c + 1 < NC) asm volatile("cp.async.wait_group 0;");
        __syncthreads();
    }

    // ---- epilogue ----
#pragma unroll
    for (int i = 0; i < MT; i++) {
        int row0 = m0 + m0w + i * 16 + (lid >> 2);
#pragma unroll
        for (int half = 0; half < 2; half++) {
            int co = row0 + half * 8;
            if (co >= Cout) continue;
            float bv = bias[co];
            size_t rbase = ((size_t)b * Cout + co) * HWOUT + hw0 + n0w + (lid & 3) * 2;
#pragma unroll
            for (int jn = 0; jn < 2; jn++) {
                float v0 = acc[i][jn][half * 2 + 0] + bv;
                float v1 = acc[i][jn][half * 2 + 1] + bv;
                size_t o = rbase + jn * 8;
                if (EPI == 1) {
                    float2 s = *(const float2*)(epi_src + o);
                    v0 = fmaxf(v0, 0.f) + s.x; v1 = fmaxf(v1, 0.f) + s.y;
                } else if (EPI == 2) {
                    float2 s = *(const float2*)(epi_src + o);
                    v0 += s.x; v1 += s.y;
                }
                *(float2*)(out + o) = make_float2(v0, v1);
            }
        }
    }
}

// MT=4: A 4*32KB=128KB, B 32KB (+ meta 24KB for deform)
#define SMEM_DEF  (4*256*128 + 32768 + 24576)   // 188416
#define SMEM_RES  (4*256*128 + 32768)           // 163840
#define SMEM_COM  (4*64*128 + 32768)            // 65536

extern "C" void kernel_launch(void* const* d_in, const int* in_sizes, int n_in,
                              void* d_out, int out_size)
{
    const float* f0 = (const float*)d_in[0];
    const float* f1 = (const float*)d_in[1];
    const float* f2 = (const float*)d_in[2];
    const float* com_w[2] = {(const float*)d_in[3], (const float*)d_in[5]};
    const float* com_b[2] = {(const float*)d_in[4], (const float*)d_in[6]};
    const float* dcn_w[2] = {(const float*)d_in[7], (const float*)d_in[9]};
    const float* dcn_b[2] = {(const float*)d_in[8], (const float*)d_in[10]};
    const float* res_w = (const float*)d_in[11];
    const float* res_b = (const float*)d_in[12];
    float* out = (float*)d_out;

    float *gf, *gom;
    __nv_bfloat16 *wdef, *wcom, *wres;
    cudaGetSymbolAddress((void**)&gf,   g_f);
    cudaGetSymbolAddress((void**)&gom,  g_om);
    cudaGetSymbolAddress((void**)&wdef, g_wdef);
    cudaGetSymbolAddress((void**)&wcom, g_wcom);
    cudaGetSymbolAddress((void**)&wres, g_wres);

    cudaFuncSetAttribute(tc_gemm<0,0,1>, cudaFuncAttributeMaxDynamicSharedMemorySize, SMEM_COM);
    cudaFuncSetAttribute(tc_gemm<1,1,4>, cudaFuncAttributeMaxDynamicSharedMemorySize, SMEM_DEF);
    cudaFuncSetAttribute(tc_gemm<0,2,4>, cudaFuncAttributeMaxDynamicSharedMemorySize, SMEM_RES);

    cudaMemcpyAsync(gf, f2, sizeof(float) * BATCH * CIN * HWOUT, cudaMemcpyDeviceToDevice);

    const int nd = 256 * KDEF;
    const int nc = 64 * KCONV;
    const int nr = 256 * KCONV;
    for (int l = 0; l < 2; l++) {
        prep_w<<<(nd + 255) / 256, 256>>>(dcn_w[l], wdef + (size_t)l*2*nd, wdef + (size_t)l*2*nd + nd, 256, 256, KDEF);
        prep_w<<<(nc + 255) / 256, 256>>>(com_w[l], wcom + (size_t)l*2*nc, wcom + (size_t)l*2*nc + nc,  48, 64, KCONV);
    }
    prep_w<<<(nr + 255) / 256, 256>>>(res_w, wres, wres + nr, 256, 256, KCONV);

    const float* feats[2] = {f1, f0};
    const int Hins[2]    = {80, 160};
    const int strides[2] = {2, 4};
    const int pads[2]    = {1, 3};
    const int dils[2]    = {1, 3};

    for (int rep = 0; rep < 2; rep++) {
        for (int l = 0; l < 2; l++) {
            tc_gemm<0,0,1><<<dim3(100, 1), NTHREADS, SMEM_COM>>>(
                gf, 40, 40,
                wcom + (size_t)l*2*nc, wcom + (size_t)l*2*nc + nc,
                com_b[l], nullptr, nullptr, gom, 48, KCONV, 1, 1, 1);
            tc_gemm<1,1,4><<<dim3(100, 1), NTHREADS, SMEM_DEF>>>(
                feats[l], Hins[l], Hins[l],
                wdef + (size_t)l*2*nd, wdef + (size_t)l*2*nd + nd,
                dcn_b[l], gom, gf, gf, 256, KDEF, strides[l], pads[l], dils[l]);
        }
    }
    tc_gemm<0,2,4><<<dim3(100, 1), NTHREADS, SMEM_RES>>>(
        gf, 40, 40, wres, wres + nr, res_b, nullptr, f2, out, 256, KCONV, 1, 1, 1);
}

// round 9
// speedup vs baseline: 2.2724x; 1.0194x over previous
#include <cuda_runtime.h>
#include <cuda_bf16.h>
#include <math.h>
#include <stdint.h>

#define WOUT 40
#define HWOUT 1600
#define CIN 256
#define BATCH 4

#define BN 64
#define KC 64
#define NTHREADS 512
#define GRID 100
#define KDEF (CIN*16)
#define KCONV (CIN*9)

#define ND (256*KDEF)      // deform weight elems per fmt
#define NCOM (64*KCONV)    // com weight elems per fmt (padded 64 rows)
#define NRES (256*KCONV)

// fixed smem regions (bytes): A [0,131072) B(MT4) [131072,163840) OM [163840,176128)
#define OFF_OM 163840
#define SMEM_TOTAL 176128

// ---------------- device scratch ----------------
__device__ float g_f[BATCH*CIN*HWOUT];
__device__ __align__(16) __nv_bfloat16 g_wdef[2*2*ND];
__device__ __align__(16) __nv_bfloat16 g_wcom[2*2*NCOM];
__device__ __align__(16) __nv_bfloat16 g_wres[2*NRES];
__device__ unsigned int g_cnt[8];

__device__ __forceinline__ uint32_t smem_u32(const void* p) {
    uint32_t a;
    asm("{ .reg .u64 t; cvta.to.shared.u64 t, %1; cvt.u32.u64 %0, t; }" : "=r"(a) : "l"(p));
    return a;
}
__device__ __forceinline__ uint32_t sw128(uint32_t o) { return o ^ ((o >> 3) & 0x70); }

__device__ __forceinline__ void ldsm4(uint32_t* r, uint32_t addr) {
    asm volatile("ldmatrix.sync.aligned.m8n8.x4.shared.b16 {%0,%1,%2,%3}, [%4];"
        : "=r"(r[0]), "=r"(r[1]), "=r"(r[2]), "=r"(r[3]) : "r"(addr));
}
__device__ __forceinline__ void mma16816(float* c, const uint32_t* a, uint32_t b0, uint32_t b1) {
    asm volatile("mma.sync.aligned.m16n8k16.row.col.f32.bf16.bf16.f32 "
        "{%0,%1,%2,%3},{%4,%5,%6,%7},{%8,%9},{%0,%1,%2,%3};"
        : "+f"(c[0]), "+f"(c[1]), "+f"(c[2]), "+f"(c[3])
        : "r"(a[0]), "r"(a[1]), "r"(a[2]), "r"(a[3]), "r"(b0), "r"(b1));
}

// monotone-counter grid barrier: safe across graph replays (gen = old/GRID)
__device__ __forceinline__ void grid_bar(int slot) {
    __syncthreads();
    if (threadIdx.x == 0) {
        __threadfence();
        unsigned int old = atomicAdd(&g_cnt[slot], 1u);
        unsigned int target = (old / GRID) * GRID + GRID;
        while (*(volatile unsigned int*)&g_cnt[slot] < target) __nanosleep(64);
    }
    __syncthreads();
}

// MODE 0: implicit-GEMM 3x3 conv (s1 p1, x read via __ldcg — x is mutable gf).
// MODE 1: modulated deformable conv (k=4, K=16), offsets from smem om tile.
// EPI 0: +bias ; 1: relu(v+bias)+__ldcg(epi_src) ; 2: v+bias+__ldcg(epi_src) ; 3: +bias -> smem om tile
template<int MODE, int EPI, int MT>
__device__ void stage_gemm(char* smem, int bx,
        const float* __restrict__ x, int Hin, int Win,
        const __nv_bfloat16* __restrict__ whi, const __nv_bfloat16* __restrict__ wlo,
        const float* __restrict__ bias,
        float* som, const float* __restrict__ epi_src, float* __restrict__ out,
        int Cout, int Ktot, int stride, int pad, int dil)
{
    constexpr int BM = MT * 64;
    constexpr int ABUF = BM * 128;
    constexpr int OFF_B = 4 * ABUF;

    const uint32_t sb = smem_u32(smem);
    const int tid = threadIdx.x;
    const int wid = tid >> 5, lid = tid & 31;
    const int n0 = bx * BN;
    const int b  = n0 / HWOUT;
    const int hw0 = n0 - b * HWOUT;
    const int HWin = Hin * Win;
    const float* xb = x + (size_t)b * CIN * HWin;

    __syncthreads();   // previous stage fully done with smem

    const int pxT = tid & 63;
    const int grpT = tid >> 6;
    const uint32_t xorv = (uint32_t)((pxT & 7) << 4);
    const uint32_t rowb = (uint32_t)(pxT * 128);

    // ---- per-thread sampling meta (deform): from smem om tile, held in regs ----
    int2 ad[2]; float4 wq[2];
    if (MODE == 1) {
#pragma unroll
        for (int u = 0; u < 2; u++) {
            int k = 2 * grpT + u;
            int hw = hw0 + pxT;
            int h = hw / WOUT, w = hw - h * WOUT;
            float dy = som[(2*k  ) * 64 + pxT];
            float dx = som[(2*k+1) * 64 + pxT];
            float mm = som[(32+k ) * 64 + pxT];
            mm = 1.0f / (1.0f + expf(-mm));
            float py = (float)((k >> 2) * dil + h * stride - pad) + dy;
            float px = (float)((k &  3) * dil + w * stride - pad) + dx;
            float fy = floorf(py), fx = floorf(px);
            int y0 = (int)fy, x0 = (int)fx;
            int y1 = y0 + 1, x1 = x0 + 1;
            float ly = py - fy, lx = px - fx;
            float wy0 = ((y0 >= 0) & (y0 < Hin)) ? (1.f - ly) * mm : 0.f;
            float wy1 = ((y1 >= 0) & (y1 < Hin)) ? ly * mm : 0.f;
            float wx0 = ((x0 >= 0) & (x0 < Win)) ? (1.f - lx) : 0.f;
            float wx1 = ((x1 >= 0) & (x1 < Win)) ? lx : 0.f;
            int xL = min(max(x0, 0), Win - 2);
            float wL = (x0 == xL ? wx0 : 0.f) + (x1 == xL ? wx1 : 0.f);
            float wR = (x0 == xL + 1 ? wx0 : 0.f) + (x1 == xL + 1 ? wx1 : 0.f);
            int yT = min(max(y0, 0), Hin - 1);
            int yB = min(max(y1, 0), Hin - 1);
            ad[u] = make_int2(yT * Win + xL, (yB - yT) * Win);
            wq[u] = make_float4(wy0 * wL, wy0 * wR, wy1 * wL, wy1 * wR);
        }
    }

    float acc[MT][2][4];
#pragma unroll
    for (int i = 0; i < MT; i++)
#pragma unroll
        for (int j = 0; j < 2; j++)
#pragma unroll
            for (int q = 0; q < 4; q++) acc[i][j][q] = 0.f;

    const int NC = Ktot / KC;
    const int wm = wid & 3, wn = wid >> 2;
    const int m0w = wm * (MT * 16);
    const int n0w = wn * 16;

    auto loadA_async = [&](int c, int buf) {
        const int k0 = c * KC;
        constexpr int TOT = BM * 16;
#pragma unroll
        for (int s = 0; s < TOT / NTHREADS; s++) {
            int f = tid + s * NTHREADS;
            int fmt = f / (BM * 8);
            int rem = f - fmt * (BM * 8);
            int r = rem >> 3, j = rem & 7;
            const __nv_bfloat16* src = fmt ? wlo : whi;
            uint32_t dst = sb + (uint32_t)((buf*2 + fmt) * ABUF) + sw128((uint32_t)(r*128 + j*16));
            const void* gsrc = src + (size_t)r * Ktot + k0 + j * 8;
            asm volatile("cp.async.cg.shared.global [%0], [%1], 16;" :: "r"(dst), "l"(gsrc));
        }
        asm volatile("cp.async.commit_group;");
    };

    auto gatherB_def = [&](int c, int buf) {
#pragma unroll
        for (int ciL = 0; ciL < 4; ciL++) {
            const float* plane = xb + (size_t)(c * 4 + ciL) * HWin;
            const float* p0 = plane + ad[0].x;
            const float* p1 = plane + ad[1].x;
            float v0 = wq[0].x*p0[0] + wq[0].y*p0[1] + wq[0].z*p0[ad[0].y] + wq[0].w*p0[ad[0].y+1];
            float v1 = wq[1].x*p1[0] + wq[1].y*p1[1] + wq[1].z*p1[ad[1].y] + wq[1].w*p1[ad[1].y+1];
            __nv_bfloat162 hh = __floats2bfloat162_rn(v0, v1);
            float l0 = v0 - __bfloat162float(hh.x);
            float l1 = v1 - __bfloat162float(hh.y);
            __nv_bfloat162 ll = __floats2bfloat162_rn(l0, l1);
            uint32_t so = rowb + (((uint32_t)(ciL * 32 + grpT * 4)) ^ xorv);
            *(uint32_t*)(smem + OFF_B + (buf*2 + 0) * 8192 + so) = *(uint32_t*)&hh;
            *(uint32_t*)(smem + OFF_B + (buf*2 + 1) * 8192 + so) = *(uint32_t*)&ll;
        }
    };

    auto gatherB_conv = [&](int c, int buf) {
        int hw = hw0 + pxT;
        int h = hw / WOUT, w_ = hw - h * WOUT;
#pragma unroll
        for (int q = 0; q < 4; q++) {
            float v[2];
#pragma unroll
            for (int u = 0; u < 2; u++) {
                int k = c * KC + grpT * 8 + q * 2 + u;
                int ci = k / 9, jj = k - ci * 9;
                int y  = h + jj / 3 - 1;
                int xx = w_ + (jj - (jj / 3) * 3) - 1;
                v[u] = (y >= 0 && y < Hin && xx >= 0 && xx < Win)
                     ? __ldcg(&xb[(size_t)ci * HWin + y * Win + xx]) : 0.f;
            }
            __nv_bfloat162 hh = __floats2bfloat162_rn(v[0], v[1]);
            float l0 = v[0] - __bfloat162float(hh.x);
            float l1 = v[1] - __bfloat162float(hh.y);
            __nv_bfloat162 ll = __floats2bfloat162_rn(l0, l1);
            uint32_t so = rowb + (((uint32_t)(grpT * 16 + q * 4)) ^ xorv);
            *(uint32_t*)(smem + OFF_B + (buf*2 + 0) * 8192 + so) = *(uint32_t*)&hh;
            *(uint32_t*)(smem + OFF_B + (buf*2 + 1) * 8192 + so) = *(uint32_t*)&ll;
        }
    };

    const uint32_t aOff = (uint32_t)((m0w + (lid & 15)) * 128 + (lid >> 4) * 16);
    const uint32_t bOff = (uint32_t)((n0w + (lid & 7) + ((lid >> 4) & 1) * 8) * 128 + ((lid >> 3) & 1) * 16);

    loadA_async(0, 0);
    if (MODE == 1) gatherB_def(0, 0); else gatherB_conv(0, 0);
    asm volatile("cp.async.wait_group 0;");
    __syncthreads();

    for (int c = 0; c < NC; c++) {
        const int buf = c & 1;
        if (c + 1 < NC) {
            loadA_async(c + 1, buf ^ 1);
            if (MODE == 1) gatherB_def(c + 1, buf ^ 1); else gatherB_conv(c + 1, buf ^ 1);
        }

        const uint32_t sAh = sb + (uint32_t)((buf*2 + 0) * ABUF);
        const uint32_t sAl = sb + (uint32_t)((buf*2 + 1) * ABUF);
        const uint32_t sBh = sb + OFF_B + (buf*2 + 0) * 8192;
        const uint32_t sBl = sb + OFF_B + (buf*2 + 1) * 8192;

#pragma unroll
        for (int ks = 0; ks < 4; ks++) {
            uint32_t ah[MT][4], al[MT][4], bh[4], bl[4];
#pragma unroll
            for (int i = 0; i < MT; i++) {
                ldsm4(ah[i], sAh + sw128(aOff + (uint32_t)(i * 2048 + ks * 32)));
                ldsm4(al[i], sAl + sw128(aOff + (uint32_t)(i * 2048 + ks * 32)));
            }
            ldsm4(bh, sBh + sw128(bOff + (uint32_t)(ks * 32)));
            ldsm4(bl, sBl + sw128(bOff + (uint32_t)(ks * 32)));
#pragma unroll
            for (int i = 0; i < MT; i++)
#pragma unroll
                for (int jn = 0; jn < 2; jn++) {
                    int sel = jn * 2;
                    mma16816(acc[i][jn], ah[i], bh[sel], bh[sel + 1]);
                    mma16816(acc[i][jn], ah[i], bl[sel], bl[sel + 1]);
                    mma16816(acc[i][jn], al[i], bh[sel], bh[sel + 1]);
                }
        }
        if (c + 1 < NC) asm volatile("cp.async.wait_group 0;");
        __syncthreads();
    }

    // ---- epilogue ----
#pragma unroll
    for (int i = 0; i < MT; i++) {
        int row0 = m0w + i * 16 + (lid >> 2);
#pragma unroll
        for (int half = 0; half < 2; half++) {
            int co = row0 + half * 8;
            if (co >= Cout) continue;
            float bv = bias[co];
#pragma unroll
            for (int jn = 0; jn < 2; jn++) {
                float v0 = acc[i][jn][half * 2 + 0] + bv;
                float v1 = acc[i][jn][half * 2 + 1] + bv;
                if (EPI == 3) {
                    int cb = co * 64 + n0w + (lid & 3) * 2 + jn * 8;
                    som[cb] = v0; som[cb + 1] = v1;
                } else {
                    size_t o = ((size_t)b * Cout + co) * HWOUT + hw0 + n0w + (lid & 3) * 2 + jn * 8;
                    if (EPI == 1) {
                        float2 s = __ldcg((const float2*)(epi_src + o));
                        v0 = fmaxf(v0, 0.f) + s.x; v1 = fmaxf(v1, 0.f) + s.y;
                    } else if (EPI == 2) {
                        float2 s = __ldcg((const float2*)(epi_src + o));
                        v0 += s.x; v1 += s.y;
                    }
                    *(float2*)(out + o) = make_float2(v0, v1);
                }
            }
        }
    }
}

__global__ void __launch_bounds__(NTHREADS)
dcnfpn_persist(const float* __restrict__ f0, const float* __restrict__ f1,
               const float* __restrict__ f2,
               const float* cw0, const float* cb0, const float* cw1, const float* cb1,
               const float* dw0, const float* db0, const float* dw1, const float* db1,
               const float* rw, const float* rb, float* __restrict__ out)
{
    extern __shared__ __align__(1024) char smem[];
    const int bx = blockIdx.x;
    const int tid = threadIdx.x;
    const int gtid = bx * NTHREADS + tid;
    const int GT = GRID * NTHREADS;

    // ---- prep: weights fp32 -> bf16 hi/lo; gf = f2 ----
    {
        const float* dsrc[2] = {dw0, dw1};
        for (int l = 0; l < 2; l++) {
            __nv_bfloat16* hi = g_wdef + (size_t)l * 2 * ND;
            __nv_bfloat16* lo = hi + ND;
            for (int i = gtid; i < ND; i += GT) {
                float v = dsrc[l][i];
                __nv_bfloat16 h = __float2bfloat16(v);
                hi[i] = h; lo[i] = __float2bfloat16(v - __bfloat162float(h));
            }
        }
        const float* csrc[2] = {cw0, cw1};
        for (int l = 0; l < 2; l++) {
            __nv_bfloat16* hi = g_wcom + (size_t)l * 2 * NCOM;
            __nv_bfloat16* lo = hi + NCOM;
            for (int i = gtid; i < NCOM; i += GT) {
                int row = i / KCONV;
                float v = (row < 48) ? csrc[l][i] : 0.f;
                __nv_bfloat16 h = __float2bfloat16(v);
                hi[i] = h; lo[i] = __float2bfloat16(v - __bfloat162float(h));
            }
        }
        for (int i = gtid; i < NRES; i += GT) {
            float v = rw[i];
            __nv_bfloat16 h = __float2bfloat16(v);
            g_wres[i] = h; g_wres[NRES + i] = __float2bfloat16(v - __bfloat162float(h));
        }
        const float4* s4 = (const float4*)f2;
        float4* d4 = (float4*)g_f;
        for (int i = gtid; i < BATCH*CIN*HWOUT/4; i += GT) d4[i] = s4[i];
    }
    grid_bar(0);

    float* som = (float*)(smem + OFF_OM);
    const float* feats[2] = {f1, f0};
    const float* cb[2] = {cb0, cb1};
    const float* db[2] = {db0, db1};
    const int Hins[2] = {80, 160};
    const int strides[2] = {2, 4};
    const int pads[2] = {1, 3};
    const int dils[2] = {1, 3};

    int slot = 1;
    for (int rep = 0; rep < 2; rep++) {
        for (int l = 0; l < 2; l++) {
            // om tile (smem) = conv3x3(gf) + bias
            stage_gemm<0,3,1>(smem, bx, g_f, 40, 40,
                g_wcom + (size_t)l*2*NCOM, g_wcom + (size_t)l*2*NCOM + NCOM,
                cb[l], som, nullptr, nullptr, 48, KCONV, 1, 1, 1);
            // gf = relu(deform(feats, om) + bias) + gf   (own pixels only)
            stage_gemm<1,1,4>(smem, bx, feats[l], Hins[l], Hins[l],
                g_wdef + (size_t)l*2*ND, g_wdef + (size_t)l*2*ND + ND,
                db[l], som, g_f, g_f, 256, KDEF, strides[l], pads[l], dils[l]);
            grid_bar(slot++);   // gf halo must be complete before next com / res
        }
    }
    // out = fh + conv3x3(gf) + bias
    stage_gemm<0,2,4>(smem, bx, g_f, 40, 40,
        g_wres, g_wres + NRES, rb, nullptr, f2, out, 256, KCONV, 1, 1, 1);
}

extern "C" void kernel_launch(void* const* d_in, const int* in_sizes, int n_in,
                              void* d_out, int out_size)
{
    const float* f0 = (const float*)d_in[0];
    const float* f1 = (const float*)d_in[1];
    const float* f2 = (const float*)d_in[2];

    cudaFuncSetAttribute(dcnfpn_persist, cudaFuncAttributeMaxDynamicSharedMemorySize, SMEM_TOTAL);

    dcnfpn_persist<<<GRID, NTHREADS, SMEM_TOTAL>>>(
        f0, f1, f2,
        (const float*)d_in[3], (const float*)d_in[4],
        (const float*)d_in[5], (const float*)d_in[6],
        (const float*)d_in[7], (const float*)d_in[8],
        (const float*)d_in[9], (const float*)d_in[10],
        (const float*)d_in[11], (const float*)d_in[12],
        (float*)d_out);
}